// round 14
// baseline (speedup 1.0000x reference)
#include <cuda_runtime.h>
#include <cuda_fp16.h>
#include <cstdint>
#include <math.h>

namespace {
constexpr int B  = 2;
constexpr int T  = 2048;
constexpr int D  = 1024;
constexpr int H  = 16;
constexpr int DK = 64;
constexpr int BT = B * T;
constexpr int C  = H * DK;
constexpr int NC = T / 64;
constexpr int UNITS = B * H * NC;   // 1024
}

// ---------------- scratch ----------------
__device__ float d_qpre[BT * C];
__device__ float d_kpre[BT * C];
__device__ float d_vpre[BT * C];
__device__ float d_gpre[BT * C];
__device__ float d_q[B * H * T * DK];
__device__ float d_k[B * H * T * DK];
__device__ float d_v[B * H * T * DK];
__device__ float d_g[B * H * T];
__device__ float d_beta[B * H * T];
__device__ float d_o[BT * C];
__device__ float d_Oi[UNITS * 4096];
__device__ float d_Qe[UNITS * 4096];
__device__ float d_Sm[UNITS * 4096];
__device__ float d_Sa[UNITS * 4096];
__device__ __half d_xh[BT * D];
__device__ __half d_xl[BT * D];
__device__ __half d_Wt[5 * 1024 * 1024];   // [z][N][K] transposed weights, single fp16
__device__ __half d_ogh[BT * C];
__device__ __half d_ogl[BT * C];

__device__ __forceinline__ float siluf(float x) { return x / (1.f + expf(-x)); }

__device__ __forceinline__ uint32_t smem_to_u32(const void* smem_ptr) {
    uint32_t addr;
    asm("{ .reg .u64 tmp; cvta.to.shared.u64 tmp, %1; cvt.u32.u64 %0, tmp; }"
        : "=r"(addr) : "l"(smem_ptr));
    return addr;
}
__device__ __forceinline__ void cp16s(uint32_t saddr, const void* g) {
    asm volatile("cp.async.cg.shared.global [%0], [%1], 16;" :: "r"(saddr), "l"(g));
}
__device__ __forceinline__ void cp_commit() {
    asm volatile("cp.async.commit_group;");
}
__device__ __forceinline__ void cp_wait1() {
    asm volatile("cp.async.wait_group 1;" ::: "memory");
}
__device__ __forceinline__ void cp_wait0() {
    asm volatile("cp.async.wait_group 0;" ::: "memory");
}

#define LDSM4(r0, r1, r2, r3, addr) \
    asm volatile("ldmatrix.sync.aligned.m8n8.x4.shared.b16 {%0, %1, %2, %3}, [%4];" \
                 : "=r"(r0), "=r"(r1), "=r"(r2), "=r"(r3) : "r"(addr))

#define MMA16816H(d, a, bb0, bb1) \
    asm volatile("mma.sync.aligned.m16n8k16.row.col.f32.f16.f16.f32 " \
                 "{%0, %1, %2, %3}, {%4, %5, %6, %7}, {%8, %9}, {%0, %1, %2, %3};" \
                 : "+f"((d)[0]), "+f"((d)[1]), "+f"((d)[2]), "+f"((d)[3]) \
                 : "r"((a)[0]), "r"((a)[1]), "r"((a)[2]), "r"((a)[3]), \
                   "r"(bb0), "r"(bb1))

// ================= mma.sync fp16x2 GEMM, 128x128 tile, 2-stage, 2 CTA/SM =================
#define GEMM_ROWB 144
#define GEMM_TEN  (128 * GEMM_ROWB)            // 18432 B per tensor
#define GEMM_STAGE (3 * GEMM_TEN)              // Ah|Al|B = 55296 B
#define GSMEM_BYTES (2 * GEMM_STAGE)           // 110592 B

__global__ __launch_bounds__(256, 2) void gemm_mma_kernel(
    const __half* __restrict__ Ah, const __half* __restrict__ Al,
    const __half* __restrict__ Wt,
    float* __restrict__ C0, float* __restrict__ C1,
    float* __restrict__ C2, float* __restrict__ C3)
{
    extern __shared__ unsigned char gsm[];
    const uint32_t sbase = smem_to_u32(gsm);

    const int tid = threadIdx.x;
    const int wid = tid >> 5;
    const int lane = tid & 31;
    const int z = blockIdx.z;

    const __half* Bw = Wt + (size_t)z * 1048576;
    float* Cout = (z == 0) ? C0 : (z == 1) ? C1 : (z == 2) ? C2 : C3;

    const size_t arow0 = (size_t)blockIdx.y * 128;
    const size_t brow0 = (size_t)blockIdx.x * 128;

    const int wm = wid >> 1;
    const int wn = wid & 1;
    const int m0 = wm * 32;
    const int n0 = wn * 64;

    const int a_row  = (lane & 7) + ((lane >> 3) & 1) * 8;
    const int a_colh = (lane >> 4) * 8;
    const int b_nrow = (lane & 7) + (lane >> 4) * 8;
    const int b_kh   = ((lane >> 3) & 1) * 8;

    float acc[2][8][4];
#pragma unroll
    for (int mt = 0; mt < 2; mt++)
#pragma unroll
        for (int nt = 0; nt < 8; nt++)
#pragma unroll
            for (int e = 0; e < 4; e++) acc[mt][nt][e] = 0.f;

#define LOAD_STAGE(chunk_i, stage_i) do {                                        \
        const int koff_ = (chunk_i) * 64;                                        \
        const uint32_t stb_ = sbase + (stage_i) * GEMM_STAGE;                    \
        for (int i_ = 0; i_ < 12; i_++) {                                        \
            int p_ = tid + i_ * 256;                                             \
            int sel_ = p_ >> 10;                                                 \
            int q_ = p_ & 1023;                                                  \
            int r_ = q_ >> 3;                                                    \
            int e_ = q_ & 7;                                                     \
            const __half* src_ = (sel_ == 0) ? Ah : (sel_ == 1) ? Al : Bw;       \
            size_t row_ = ((sel_ < 2) ? arow0 : brow0) + r_;                     \
            uint32_t dsm_ = stb_ + sel_ * GEMM_TEN + r_ * GEMM_ROWB + e_ * 16;   \
            cp16s(dsm_, src_ + row_ * 1024 + koff_ + e_ * 8);                    \
        }                                                                        \
        cp_commit();                                                             \
    } while (0)

#define LOAD_A(ks_, bf_) do {                                                     \
        _Pragma("unroll")                                                         \
        for (int mt_ = 0; mt_ < 2; mt_++) {                                       \
            uint32_t off_ = (uint32_t)((m0 + mt_ * 16 + a_row) * GEMM_ROWB        \
                                       + ((ks_) * 16 + a_colh) * 2);              \
            LDSM4(ahb[bf_][mt_][0], ahb[bf_][mt_][1], ahb[bf_][mt_][2],           \
                  ahb[bf_][mt_][3], bAh + off_);                                  \
            LDSM4(alb[bf_][mt_][0], alb[bf_][mt_][1], alb[bf_][mt_][2],           \
                  alb[bf_][mt_][3], bAl + off_);                                  \
        }                                                                         \
    } while (0)

    LOAD_STAGE(0, 0);

    for (int c = 0; c < 16; c++) {
        if (c + 1 < 16) {
            LOAD_STAGE(c + 1, (c + 1) & 1);
            cp_wait1();
        } else {
            cp_wait0();
        }
        __syncthreads();

        const uint32_t stb = sbase + (c & 1) * GEMM_STAGE;
        const uint32_t bAh = stb;
        const uint32_t bAl = stb + GEMM_TEN;
        const uint32_t bB  = stb + 2 * GEMM_TEN;

        uint32_t ahb[2][2][4], alb[2][2][4];
        LOAD_A(0, 0);

#pragma unroll
        for (int ks = 0; ks < 4; ks++) {
            const int cur = ks & 1;
            const int nxt = cur ^ 1;
            if (ks < 3) LOAD_A(ks + 1, nxt);

#pragma unroll
            for (int np = 0; np < 4; np++) {
                uint32_t off = (uint32_t)((n0 + np * 16 + b_nrow) * GEMM_ROWB + (ks * 16 + b_kh) * 2);
                uint32_t b0, b1, b2, b3;
                LDSM4(b0, b1, b2, b3, bB + off);
#pragma unroll
                for (int mt = 0; mt < 2; mt++) {
                    MMA16816H(acc[mt][np * 2], ahb[cur][mt], b0, b1);
                    MMA16816H(acc[mt][np * 2], alb[cur][mt], b0, b1);
                    MMA16816H(acc[mt][np * 2 + 1], ahb[cur][mt], b2, b3);
                    MMA16816H(acc[mt][np * 2 + 1], alb[cur][mt], b2, b3);
                }
            }
        }
        __syncthreads();
    }
#undef LOAD_STAGE
#undef LOAD_A

    const int er = lane >> 2;
    const int ec = (lane & 3) * 2;
#pragma unroll
    for (int mt = 0; mt < 2; mt++) {
#pragma unroll
        for (int nt = 0; nt < 8; nt++) {
            size_t row = arow0 + m0 + mt * 16 + er;
            size_t col = brow0 + n0 + nt * 8 + ec;
            float2 v0 = make_float2(acc[mt][nt][0], acc[mt][nt][1]);
            float2 v1 = make_float2(acc[mt][nt][2], acc[mt][nt][3]);
            *reinterpret_cast<float2*>(Cout + row * 1024 + col) = v0;
            *reinterpret_cast<float2*>(Cout + (row + 8) * 1024 + col) = v1;
        }
    }
}

// ---------------- fused prep: splitx | wsplit | gbeta (1-D grid dispatch) ----------------
__global__ __launch_bounds__(256) void prep_kernel(
    const float* __restrict__ x,
    const float* __restrict__ Wq, const float* __restrict__ Wk, const float* __restrict__ Wv,
    const float* __restrict__ Wg, const float* __restrict__ Wo,
    const float* __restrict__ Wa, const float* __restrict__ Wb,
    const float* __restrict__ A_log, const float* __restrict__ dt_bias)
{
    __shared__ float pool[64 * 33 + 32 * 32];
    const int bx = blockIdx.x;
    const int tid = threadIdx.x;

    if (bx < 4096) {
        // ---- splitx ----
        const int i0 = (bx * 256 + tid) * 4;
        float4 v = *reinterpret_cast<const float4*>(x + i0);
        float vv[4];
        vv[0] = v.x; vv[1] = v.y; vv[2] = v.z; vv[3] = v.w;
        for (int j = 0; j < 4; j++) {
            __half hb = __float2half_rn(vv[j]);
            d_xh[i0 + j] = hb;
            d_xl[i0 + j] = __float2half_rn(vv[j] - __half2float(hb));
        }
    } else if (bx < 4096 + 5120) {
        // ---- wsplit ----
        float* ts = pool;                          // [32][33]
        const int wbx = bx - 4096;
        const int z = wbx >> 10;                   // 0..4
        const int n0 = (wbx & 31) * 32;
        const int k0 = ((wbx >> 5) & 31) * 32;
        const float* W = (z == 0) ? Wq : (z == 1) ? Wk : (z == 2) ? Wv : (z == 3) ? Wg : Wo;
        const int txx = tid & 31, tyy = tid >> 5;
        for (int j = 0; j < 4; j++)
            ts[(tyy + 8 * j) * 33 + txx] = W[(size_t)(k0 + tyy + 8 * j) * 1024 + n0 + txx];
        __syncthreads();
        __half* ot = d_Wt + (size_t)z * 1048576;
        for (int j = 0; j < 4; j++) {
            float v = ts[txx * 33 + tyy + 8 * j];
            size_t idx = (size_t)(n0 + tyy + 8 * j) * 1024 + k0 + txx;
            ot[idx] = __float2half_rn(v);
        }
    } else {
        // ---- gbeta ----
        float* xs = pool;                          // [64][33]
        float* ws = pool + 64 * 33;                // [32][32]
        const int row0 = (bx - 9216) * 64;
        const int cc = tid & 31, rr = tid >> 5;

        float acc[8];
        for (int i = 0; i < 8; i++) acc[i] = 0.f;

        for (int k0 = 0; k0 < 1024; k0 += 32) {
            {
                int r = tid >> 3, c4 = (tid & 7) * 4;
                for (int pp = 0; pp < 2; pp++) {
                    float4 v = *reinterpret_cast<const float4*>(
                        x + (size_t)(row0 + r + pp * 32) * 1024 + k0 + c4);
                    xs[(r + pp * 32) * 33 + c4] = v.x;
                    xs[(r + pp * 32) * 33 + c4 + 1] = v.y;
                    xs[(r + pp * 32) * 33 + c4 + 2] = v.z;
                    xs[(r + pp * 32) * 33 + c4 + 3] = v.w;
                }
            }
            for (int i = 0; i < 4; i++) {
                int p = tid + i * 256;
                int kk = p >> 5, col = p & 31;
                ws[kk * 32 + col] = (col < 16) ? Wa[(size_t)(k0 + kk) * 16 + col]
                                               : Wb[(size_t)(k0 + kk) * 16 + col - 16];
            }
            __syncthreads();
            for (int i = 0; i < 8; i++) {
                const float* xr = &xs[(rr + i * 8) * 33];
                float a = acc[i];
                for (int kk = 0; kk < 32; kk++) a = fmaf(xr[kk], ws[kk * 32 + cc], a);
                acc[i] = a;
            }
            __syncthreads();
        }

        for (int i = 0; i < 8; i++) {
            const int row = row0 + rr + i * 8;
            const int b = row >> 11, t = row & 2047;
            if (cc < 16) {
                const int h = cc;
                float zz = acc[i] + dt_bias[h];
                float sp = (zz > 20.f) ? zz : log1pf(expf(zz));
                d_g[(size_t)(b * H + h) * T + t] = -expf(A_log[h]) * sp;
            } else {
                const int h = cc - 16;
                d_beta[(size_t)(b * H + h) * T + t] = 1.f / (1.f + expf(-acc[i]));
            }
        }
    }
}

// ---------------- fused conv + silu + l2norm + relayout (4 t per thread) ----------------
__global__ __launch_bounds__(256) void convnorm_kernel(
    const float* __restrict__ wq, const float* __restrict__ wk, const float* __restrict__ wv)
{
    __shared__ float red[8][4];
    const int which = blockIdx.z;
    const int tid = threadIdx.x;
    const int idx = blockIdx.x * 256 + tid;
    const int c = idx & (C - 1);
    const int bt4 = idx >> 10;
    const int t4 = bt4 & (T / 4 - 1);
    const int b = bt4 >> 9;
    const int t0 = t4 * 4;

    const float* src = which == 0 ? d_qpre : which == 1 ? d_kpre : d_vpre;
    const float* w = which == 0 ? wq : which == 1 ? wk : wv;
    float* dst = which == 0 ? d_q : which == 1 ? d_k : d_v;

    float4 w4 = *reinterpret_cast<const float4*>(w + c * 4);
    float wr[4];
    wr[0] = w4.x; wr[1] = w4.y; wr[2] = w4.z; wr[3] = w4.w;

    const float* srow = src + (size_t)(b * T) * C + c;
    float xv[7];
    for (int j = 0; j < 7; j++) {
        int tt = t0 - 3 + j;
        xv[j] = (tt >= 0) ? srow[(size_t)tt * C] : 0.f;
    }

    float acc[4];
    for (int k = 0; k < 4; k++) {
        float a = 0.f;
        for (int j = 0; j < 4; j++) a = fmaf(xv[k + j], wr[j], a);
        acc[k] = siluf(a);
    }

    const int h = c >> 6, dk = c & 63;
    float* drow = dst + (((size_t)(b * H + h)) * T + t0) * DK + dk;

    if (which == 2) {
        for (int k = 0; k < 4; k++) drow[(size_t)k * DK] = acc[k];
        return;
    }

    // l2 norm over the 64 dk of each (h, t) row; dk spread over 2 warps.
    const int warp = tid >> 5;
    const int lane = tid & 31;
    float ss[4];
    for (int k = 0; k < 4; k++) {
        float s = acc[k] * acc[k];
        for (int o = 16; o; o >>= 1) s += __shfl_xor_sync(0xffffffffu, s, o);
        ss[k] = s;
    }
    if (lane == 0) {
        for (int k = 0; k < 4; k++) red[warp][k] = ss[k];
    }
    __syncthreads();
    const int g = tid >> 6;                      // h-group within block
    const float qs = (which == 0) ? 0.125f : 1.f;
    for (int k = 0; k < 4; k++) {
        float tot = red[g * 2][k] + red[g * 2 + 1][k];
        float r = rsqrtf(tot + 1e-6f) * qs;
        drow[(size_t)k * DK] = acc[k] * r;
    }
}

// ================= chunked delta rule =================
#define PA 68
__global__ __launch_bounds__(256) void phaseA_kernel()
{
    extern __shared__ float smA[];
    float* Ks = smA;
    float* Kt = Ks + 64 * PA;
    float* Qs = Kt + 64 * PA;
    float* U0 = Qs + 64 * PA;
    float* Ws = U0 + 64 * PA;
    float* Ms = Ws + 64 * PA;
    float* cs = Ms + 64 * PA;
    float* es = cs + 64;
    float* bv = es + 64;
    float* gv = bv + 64;

    const int unit = blockIdx.x;
    const int chunk = unit & (NC - 1);
    const int bh = unit >> 5;
    const int tid = threadIdx.x;
    const int t0 = chunk * 64;
    const int tx = tid & 15, ty = tid >> 4;

    const float* qg = d_q + ((size_t)bh * T + t0) * DK;
    const float* kg = d_k + ((size_t)bh * T + t0) * DK;
    const float* vg = d_v + ((size_t)bh * T + t0) * DK;

#pragma unroll
    for (int i = 0; i < 4; i++) {
        int p = tid + i * 256;
        int r = p >> 4, c4 = (p & 15) * 4;
        *reinterpret_cast<float4*>(Ks + r * PA + c4) = *reinterpret_cast<const float4*>(kg + r * 64 + c4);
        *reinterpret_cast<float4*>(Qs + r * PA + c4) = *reinterpret_cast<const float4*>(qg + r * 64 + c4);
        *reinterpret_cast<float4*>(U0 + r * PA + c4) = *reinterpret_cast<const float4*>(vg + r * 64 + c4);
    }
    if (tid < 64) {
        gv[tid] = d_g[(size_t)bh * T + t0 + tid];
        bv[tid] = d_beta[(size_t)bh * T + t0 + tid];
    }
    __syncthreads();
    if (tid == 0) {
        float cacc = 0.f;
        for (int t = 0; t < 64; t++) { cacc += gv[t]; cs[t] = cacc; }
    }
    __syncthreads();
    if (tid < 64) {
        es[tid] = expf(cs[tid]);
        gv[tid] = expf(cs[63] - cs[tid]);
    }
    __syncthreads();
#pragma unroll
    for (int i = 0; i < 16; i++) {
        int p = tid + i * 256;
        int r = p >> 6, ccx = p & 63;
        float kvv = Ks[r * PA + ccx];
        Kt[ccx * PA + r] = kvv;
        Ws[r * PA + ccx] = bv[r] * es[r] * kvv;
        U0[r * PA + ccx] *= bv[r];
    }
    __syncthreads();

#define P1(Aptr, Bptr)                                                            \
    {                                                                             \
        _Pragma("unroll")                                                         \
        for (int i = 0; i < 4; i++)                                               \
            _Pragma("unroll")                                                     \
            for (int j = 0; j < 4; j++) acc[i][j] = 0.f;                          \
        for (int d4 = 0; d4 < 16; d4++) {                                         \
            float4 av[4];                                                         \
            _Pragma("unroll")                                                     \
            for (int i = 0; i < 4; i++)                                           \
                av[i] = *reinterpret_cast<const float4*>((Aptr) + (ty * 4 + i) * PA + d4 * 4); \
            const float* ap = reinterpret_cast<const float*>(av);                 \
            _Pragma("unroll")                                                     \
            for (int u = 0; u < 4; u++) {                                         \
                float4 rb = *reinterpret_cast<const float4*>((Bptr) + (d4 * 4 + u) * PA + tx * 4); \
                _Pragma("unroll")                                                 \
                for (int i = 0; i < 4; i++) {                                     \
                    float a = ap[i * 4 + u];                                      \
                    acc[i][0] = fmaf(a, rb.x, acc[i][0]);                         \
                    acc[i][1] = fmaf(a, rb.y, acc[i][1]);                         \
                    acc[i][2] = fmaf(a, rb.z, acc[i][2]);                         \
                    acc[i][3] = fmaf(a, rb.w, acc[i][3]);                         \
                }                                                                 \
            }                                                                     \
        }                                                                         \
    }
#define P2(Aptr, Bptr)                                                            \
    {                                                                             \
        _Pragma("unroll")                                                         \
        for (int i = 0; i < 4; i++)                                               \
            _Pragma("unroll")                                                     \
            for (int j = 0; j < 4; j++) acc[i][j] = 0.f;                          \
        for (int s = 0; s < 64; s++) {                                            \
            float4 ra = *reinterpret_cast<const float4*>((Aptr) + s * PA + ty * 4); \
            float4 rb = *reinterpret_cast<const float4*>((Bptr) + s * PA + tx * 4); \
            const float* rap = reinterpret_cast<const float*>(&ra);               \
            _Pragma("unroll")                                                     \
            for (int i = 0; i < 4; i++) {                                         \
                float a = rap[i];                                                 \
                acc[i][0] = fmaf(a, rb.x, acc[i][0]);                             \
                acc[i][1] = fmaf(a, rb.y, acc[i][1]);                             \
                acc[i][2] = fmaf(a, rb.z, acc[i][2]);                             \
                acc[i][3] = fmaf(a, rb.w, acc[i][3]);                             \
            }                                                                     \
        }                                                                         \
    }

    float acc[4][4];

    P1(Ks, Kt);
#pragma unroll
    for (int i = 0; i < 4; i++) {
        int t = ty * 4 + i;
#pragma unroll
        for (int j = 0; j < 4; j++) {
            int s = tx * 4 + j;
            Ms[t * PA + s] = (t > s) ? bv[t] * expf(cs[t] - cs[s]) * acc[i][j] : 0.f;
        }
    }
    __syncthreads();

    for (int t = 1; t < 64; t++) {
        if (tid < 128) {
            const int j = tid & 63;
            float* X = (tid < 64) ? U0 : Ws;
            float a0 = 0.f, a1 = 0.f, a2 = 0.f, a3 = 0.f;
            const float* mrow = Ms + t * PA;
            int s = 0;
            for (; s + 4 <= t; s += 4) {
                a0 = fmaf(mrow[s],     X[s * PA + j],       a0);
                a1 = fmaf(mrow[s + 1], X[(s + 1) * PA + j], a1);
                a2 = fmaf(mrow[s + 2], X[(s + 2) * PA + j], a2);
                a3 = fmaf(mrow[s + 3], X[(s + 3) * PA + j], a3);
            }
            for (; s < t; s++) a0 = fmaf(mrow[s], X[s * PA + j], a0);
            X[t * PA + j] -= (a0 + a1) + (a2 + a3);
        }
        __syncthreads();
    }

    P1(Qs, Kt);
#pragma unroll
    for (int i = 0; i < 4; i++) {
        int t = ty * 4 + i;
#pragma unroll
        for (int j = 0; j < 4; j++) {
            int s = tx * 4 + j;
            Ms[t * PA + s] = (t >= s) ? expf(cs[t] - cs[s]) * acc[i][j] : 0.f;
        }
    }
#pragma unroll
    for (int i = 0; i < 16; i++) {
        int p = tid + i * 256;
        int r = p >> 6, ccx = p & 63;
        Ks[r * PA + ccx] *= gv[r];
    }
    __syncthreads();

    float* oOi = d_Oi + (size_t)unit * 4096;
    float* oQe = d_Qe + (size_t)unit * 4096;
    float* oSm = d_Sm + (size_t)unit * 4096;
    float* oSa = d_Sa + (size_t)unit * 4096;

    P1(Ms, U0);
#pragma unroll
    for (int i = 0; i < 4; i++)
        *reinterpret_cast<float4*>(oOi + (ty * 4 + i) * 64 + tx * 4) =
            make_float4(acc[i][0], acc[i][1], acc[i][2], acc[i][3]);

    P1(Ms, Ws);
#pragma unroll
    for (int i = 0; i < 4; i++) {
        int t = ty * 4 + i;
        float4 q4 = *reinterpret_cast<const float4*>(Qs + t * PA + tx * 4);
        float e = es[t];
        *reinterpret_cast<float4*>(oQe + t * 64 + tx * 4) =
            make_float4(e * q4.x - acc[i][0], e * q4.y - acc[i][1],
                        e * q4.z - acc[i][2], e * q4.w - acc[i][3]);
    }

    P2(Ks, Ws);
    {
        float ecc = es[63];
#pragma unroll
        for (int i = 0; i < 4; i++) {
            int a = ty * 4 + i;
            float4 v4;
            v4.x = ((a == tx * 4 + 0) ? ecc : 0.f) - acc[i][0];
            v4.y = ((a == tx * 4 + 1) ? ecc : 0.f) - acc[i][1];
            v4.z = ((a == tx * 4 + 2) ? ecc : 0.f) - acc[i][2];
            v4.w = ((a == tx * 4 + 3) ? ecc : 0.f) - acc[i][3];
            *reinterpret_cast<float4*>(oSm + a * 64 + tx * 4) = v4;
        }
    }
    P2(Ks, U0);
#pragma unroll
    for (int i = 0; i < 4; i++)
        *reinterpret_cast<float4*>(oSa + (ty * 4 + i) * 64 + tx * 4) =
            make_float4(acc[i][0], acc[i][1], acc[i][2], acc[i][3]);
#undef P1
#undef P2
}

// Phase B: 128 blocks = 32 chains x 4 dv-slices (16 cols each), sequential over chunks.
// thread = (row 0..63, colgroup 0..3 of 4 cols)
#define PB 68
#define PS2 20
__global__ __launch_bounds__(256) void phaseB_kernel()
{
    extern __shared__ float smB[];
    float* Qe = smB;                   // [64][PB]
    float* Sm = Qe + 64 * PB;          // [64][PB]
    float* Sbuf0 = Sm + 64 * PB;       // [64][PS2]
    float* Sbuf1 = Sbuf0 + 64 * PS2;

    const int bh = blockIdx.x >> 2;
    const int slice = blockIdx.x & 3;
    const int col0 = slice * 16;
    const int b = bh >> 4, h = bh & 15;
    const int tid = threadIdx.x;
    const int r = tid >> 2;            // 0..63
    const int cg = (tid & 3) * 4;      // 0,4,8,12

    for (int i = tid; i < 64 * PS2 * 2; i += 256) Sbuf0[i] = 0.f;
    __syncthreads();

    float* Sc = Sbuf0;
    float* Sn = Sbuf1;

    for (int c = 0; c < NC; c++) {
        const int unit = bh * NC + c;
        const float* qe_g = d_Qe + (size_t)unit * 4096;
        const float* sm_g = d_Sm + (size_t)unit * 4096;
#pragma unroll
        for (int i = 0; i < 4; i++) {
            int p = tid + i * 256;
            int rr = p >> 4, c4 = (p & 15) * 4;
            *reinterpret_cast<float4*>(Qe + rr * PB + c4) = *reinterpret_cast<const float4*>(qe_g + rr * 64 + c4);
            *reinterpret_cast<float4*>(Sm + rr * PB + c4) = *reinterpret_cast<const float4*>(sm_g + rr * 64 + c4);
        }
        __syncthreads();

        float4 o = *reinterpret_cast<const float4*>(d_Oi + (size_t)unit * 4096 + r * 64 + col0 + cg);
        float4 s = *reinterpret_cast<const float4*>(d_Sa + (size_t)unit * 4096 + r * 64 + col0 + cg);

        for (int d = 0; d < 64; d += 4) {
            float4 a4 = *reinterpret_cast<const float4*>(Qe + r * PB + d);
            float4 m4 = *reinterpret_cast<const float4*>(Sm + r * PB + d);
            const float* ap = reinterpret_cast<const float*>(&a4);
            const float* mp = reinterpret_cast<const float*>(&m4);
#pragma unroll
            for (int u = 0; u < 4; u++) {
                float4 rb = *reinterpret_cast<const float4*>(Sc + (d + u) * PS2 + cg);
                float a = ap[u], m = mp[u];
                o.x = fmaf(a, rb.x, o.x); o.y = fmaf(a, rb.y, o.y);
                o.z = fmaf(a, rb.z, o.z); o.w = fmaf(a, rb.w, o.w);
                s.x = fmaf(m, rb.x, s.x); s.y = fmaf(m, rb.y, s.y);
                s.z = fmaf(m, rb.z, s.z); s.w = fmaf(m, rb.w, s.w);
            }
        }

        *reinterpret_cast<float4*>(d_o + (((size_t)(b * T + c * 64 + r) * H + h) * 64 + col0 + cg)) = o;
        *reinterpret_cast<float4*>(Sn + r * PS2 + cg) = s;
        __syncthreads();
        float* tmp = Sc; Sc = Sn; Sn = tmp;
    }
}

// ---------------- gated RMSNorm -> fp16 hi/lo ----------------
__global__ __launch_bounds__(256) void rmsgate_kernel(const float* __restrict__ rms_w)
{
    const int row = blockIdx.x * 8 + (threadIdx.x >> 5);
    const int lane = threadIdx.x & 31;
    const float* orow = d_o + (size_t)row * 64;
    float2 ov = *reinterpret_cast<const float2*>(orow + lane * 2);
    float ss = ov.x * ov.x + ov.y * ov.y;
    for (int o = 16; o; o >>= 1) ss += __shfl_xor_sync(0xffffffffu, ss, o);
    const float r = rsqrtf(ss * (1.f / 64.f) + 1e-5f);

    const int bt = row >> 4, h = row & 15;
    float2 gv = *reinterpret_cast<const float2*>(d_gpre + (size_t)bt * C + h * 64 + lane * 2);
    float2 wv = *reinterpret_cast<const float2*>(rms_w + lane * 2);

    float rx = ov.x * r * wv.x * siluf(gv.x);
    float ry = ov.y * r * wv.y * siluf(gv.y);

    const size_t oidx = (size_t)bt * C + h * 64 + lane * 2;
    __half hx = __float2half_rn(rx);
    __half hy = __float2half_rn(ry);
    d_ogh[oidx] = hx;
    d_ogh[oidx + 1] = hy;
    d_ogl[oidx] = __float2half_rn(rx - __half2float(hx));
    d_ogl[oidx + 1] = __float2half_rn(ry - __half2float(hy));
}

// ---------------- launch ----------------
extern "C" void kernel_launch(void* const* d_in, const int* in_sizes, int n_in,
                              void* d_out, int out_size)
{
    const float* x       = (const float*)d_in[0];
    const float* Wq      = (const float*)d_in[1];
    const float* Wk      = (const float*)d_in[2];
    const float* Wv      = (const float*)d_in[3];
    const float* Wa      = (const float*)d_in[4];
    const float* Wb      = (const float*)d_in[5];
    const float* Wg      = (const float*)d_in[6];
    const float* Wo      = (const float*)d_in[7];
    const float* conv_q  = (const float*)d_in[8];
    const float* conv_k  = (const float*)d_in[9];
    const float* conv_v  = (const float*)d_in[10];
    const float* A_log   = (const float*)d_in[11];
    const float* dt_bias = (const float*)d_in[12];
    const float* rms_w   = (const float*)d_in[13];
    float* out = (float*)d_out;

    float *qpre, *kpre, *vpre, *gpre;
    __half *xh, *xl, *wt, *ogh, *ogl;
    cudaGetSymbolAddress((void**)&qpre, d_qpre);
    cudaGetSymbolAddress((void**)&kpre, d_kpre);
    cudaGetSymbolAddress((void**)&vpre, d_vpre);
    cudaGetSymbolAddress((void**)&gpre, d_gpre);
    cudaGetSymbolAddress((void**)&xh, d_xh);
    cudaGetSymbolAddress((void**)&xl, d_xl);
    cudaGetSymbolAddress((void**)&wt, d_Wt);
    cudaGetSymbolAddress((void**)&ogh, d_ogh);
    cudaGetSymbolAddress((void**)&ogl, d_ogl);

    const int smemA = (6 * 64 * PA + 4 * 64) * 4;
    const int smemB = (2 * 64 * PB + 2 * 64 * PS2) * 4;
    cudaFuncSetAttribute(phaseA_kernel, cudaFuncAttributeMaxDynamicSharedMemorySize, smemA);
    cudaFuncSetAttribute(phaseB_kernel, cudaFuncAttributeMaxDynamicSharedMemorySize, smemB);
    cudaFuncSetAttribute(gemm_mma_kernel, cudaFuncAttributeMaxDynamicSharedMemorySize, GSMEM_BYTES);

    // 0) fused prep: splitx (4096) | wsplit (5120) | gbeta (64)
    prep_kernel<<<9280, 256>>>(x, Wq, Wk, Wv, Wg, Wo, Wa, Wb, A_log, dt_bias);

    // 1) projections q,k,v,g
    gemm_mma_kernel<<<dim3(8, 32, 4), 256, GSMEM_BYTES>>>(
        xh, xl, wt, qpre, kpre, vpre, gpre);

    // 2) conv + silu + l2norm + relayout
    convnorm_kernel<<<dim3(BT * C / 1024, 1, 3), 256>>>(conv_q, conv_k, conv_v);

    // 3) phase A (profiled slot)
    phaseA_kernel<<<UNITS, 256, smemA>>>();

    // 4) phase B (128 blocks: 32 chains x 4 dv-slices)
    phaseB_kernel<<<B * H * 4, 256, smemB>>>();

    // 5) gated RMS norm (+ fp16 split)
    rmsgate_kernel<<<BT * H / 8, 256>>>(rms_w);

    // 6) output projection
    gemm_mma_kernel<<<dim3(8, 32, 1), 256, GSMEM_BYTES>>>(
        ogh, ogl, wt + 4ull * 1048576, out, out, out, out);
}

// round 15
// speedup vs baseline: 1.0264x; 1.0264x over previous
#include <cuda_runtime.h>
#include <cuda_fp16.h>
#include <cstdint>
#include <math.h>

namespace {
constexpr int B  = 2;
constexpr int T  = 2048;
constexpr int D  = 1024;
constexpr int H  = 16;
constexpr int DK = 64;
constexpr int BT = B * T;
constexpr int C  = H * DK;
constexpr int NC = T / 64;
constexpr int UNITS = B * H * NC;   // 1024
}

// ---------------- scratch ----------------
__device__ float d_qpre[BT * C];
__device__ float d_kpre[BT * C];
__device__ float d_vpre[BT * C];
__device__ float d_gpre[BT * C];
__device__ float d_q[B * H * T * DK];
__device__ float d_k[B * H * T * DK];
__device__ float d_v[B * H * T * DK];
__device__ float d_g[B * H * T];
__device__ float d_beta[B * H * T];
__device__ float d_o[BT * C];
__device__ float d_Oi[UNITS * 4096];
__device__ float d_Qe[UNITS * 4096];
__device__ float d_Sm[UNITS * 4096];
__device__ float d_Sa[UNITS * 4096];
__device__ __half d_xh[BT * D];
__device__ __half d_xl[BT * D];
__device__ __half d_Wt[5 * 1024 * 1024];   // [z][N][K] transposed weights, single fp16
__device__ __half d_ogh[BT * C];
__device__ __half d_ogl[BT * C];

__device__ __forceinline__ float siluf(float x) { return x / (1.f + expf(-x)); }

__device__ __forceinline__ uint32_t smem_to_u32(const void* smem_ptr) {
    uint32_t addr;
    asm("{ .reg .u64 tmp; cvta.to.shared.u64 tmp, %1; cvt.u32.u64 %0, tmp; }"
        : "=r"(addr) : "l"(smem_ptr));
    return addr;
}
__device__ __forceinline__ void cp16s(uint32_t saddr, const void* g) {
    asm volatile("cp.async.cg.shared.global [%0], [%1], 16;" :: "r"(saddr), "l"(g));
}
__device__ __forceinline__ void cp_commit() {
    asm volatile("cp.async.commit_group;");
}
__device__ __forceinline__ void cp_wait1() {
    asm volatile("cp.async.wait_group 1;" ::: "memory");
}
__device__ __forceinline__ void cp_wait0() {
    asm volatile("cp.async.wait_group 0;" ::: "memory");
}

#define LDSM4(r0, r1, r2, r3, addr) \
    asm volatile("ldmatrix.sync.aligned.m8n8.x4.shared.b16 {%0, %1, %2, %3}, [%4];" \
                 : "=r"(r0), "=r"(r1), "=r"(r2), "=r"(r3) : "r"(addr))

#define MMA16816H(d, a, bb0, bb1) \
    asm volatile("mma.sync.aligned.m16n8k16.row.col.f32.f16.f16.f32 " \
                 "{%0, %1, %2, %3}, {%4, %5, %6, %7}, {%8, %9}, {%0, %1, %2, %3};" \
                 : "+f"((d)[0]), "+f"((d)[1]), "+f"((d)[2]), "+f"((d)[3]) \
                 : "r"((a)[0]), "r"((a)[1]), "r"((a)[2]), "r"((a)[3]), \
                   "r"(bb0), "r"(bb1))

// ================= mma.sync fp16x2 GEMM, 128x128 tile, 2-stage, 2 CTA/SM =================
#define GEMM_ROWB 144
#define GEMM_TEN  (128 * GEMM_ROWB)            // 18432 B per tensor
#define GEMM_STAGE (3 * GEMM_TEN)              // Ah|Al|B = 55296 B
#define GSMEM_BYTES (2 * GEMM_STAGE)           // 110592 B

__global__ __launch_bounds__(256, 2) void gemm_mma_kernel(
    const __half* __restrict__ Ah, const __half* __restrict__ Al,
    const __half* __restrict__ Wt,
    float* __restrict__ C0, float* __restrict__ C1,
    float* __restrict__ C2, float* __restrict__ C3)
{
    extern __shared__ unsigned char gsm[];
    const uint32_t sbase = smem_to_u32(gsm);

    const int tid = threadIdx.x;
    const int wid = tid >> 5;
    const int lane = tid & 31;
    const int z = blockIdx.z;

    const __half* Bw = Wt + (size_t)z * 1048576;
    float* Cout = (z == 0) ? C0 : (z == 1) ? C1 : (z == 2) ? C2 : C3;

    const size_t arow0 = (size_t)blockIdx.y * 128;
    const size_t brow0 = (size_t)blockIdx.x * 128;

    const int wm = wid >> 1;
    const int wn = wid & 1;
    const int m0 = wm * 32;
    const int n0 = wn * 64;

    const int a_row  = (lane & 7) + ((lane >> 3) & 1) * 8;
    const int a_colh = (lane >> 4) * 8;
    const int b_nrow = (lane & 7) + (lane >> 4) * 8;
    const int b_kh   = ((lane >> 3) & 1) * 8;

    float acc[2][8][4];
#pragma unroll
    for (int mt = 0; mt < 2; mt++)
#pragma unroll
        for (int nt = 0; nt < 8; nt++)
#pragma unroll
            for (int e = 0; e < 4; e++) acc[mt][nt][e] = 0.f;

#define LOAD_STAGE(chunk_i, stage_i) do {                                        \
        const int koff_ = (chunk_i) * 64;                                        \
        const uint32_t stb_ = sbase + (stage_i) * GEMM_STAGE;                    \
        for (int i_ = 0; i_ < 12; i_++) {                                        \
            int p_ = tid + i_ * 256;                                             \
            int sel_ = p_ >> 10;                                                 \
            int q_ = p_ & 1023;                                                  \
            int r_ = q_ >> 3;                                                    \
            int e_ = q_ & 7;                                                     \
            const __half* src_ = (sel_ == 0) ? Ah : (sel_ == 1) ? Al : Bw;       \
            size_t row_ = ((sel_ < 2) ? arow0 : brow0) + r_;                     \
            uint32_t dsm_ = stb_ + sel_ * GEMM_TEN + r_ * GEMM_ROWB + e_ * 16;   \
            cp16s(dsm_, src_ + row_ * 1024 + koff_ + e_ * 8);                    \
        }                                                                        \
        cp_commit();                                                             \
    } while (0)

#define LOAD_A(ks_, bf_) do {                                                     \
        _Pragma("unroll")                                                         \
        for (int mt_ = 0; mt_ < 2; mt_++) {                                       \
            uint32_t off_ = (uint32_t)((m0 + mt_ * 16 + a_row) * GEMM_ROWB        \
                                       + ((ks_) * 16 + a_colh) * 2);              \
            LDSM4(ahb[bf_][mt_][0], ahb[bf_][mt_][1], ahb[bf_][mt_][2],           \
                  ahb[bf_][mt_][3], bAh + off_);                                  \
            LDSM4(alb[bf_][mt_][0], alb[bf_][mt_][1], alb[bf_][mt_][2],           \
                  alb[bf_][mt_][3], bAl + off_);                                  \
        }                                                                         \
    } while (0)

    LOAD_STAGE(0, 0);

    for (int c = 0; c < 16; c++) {
        if (c + 1 < 16) {
            LOAD_STAGE(c + 1, (c + 1) & 1);
            cp_wait1();
        } else {
            cp_wait0();
        }
        __syncthreads();

        const uint32_t stb = sbase + (c & 1) * GEMM_STAGE;
        const uint32_t bAh = stb;
        const uint32_t bAl = stb + GEMM_TEN;
        const uint32_t bB  = stb + 2 * GEMM_TEN;

        uint32_t ahb[2][2][4], alb[2][2][4];
        LOAD_A(0, 0);

#pragma unroll
        for (int ks = 0; ks < 4; ks++) {
            const int cur = ks & 1;
            const int nxt = cur ^ 1;
            if (ks < 3) LOAD_A(ks + 1, nxt);

#pragma unroll
            for (int np = 0; np < 4; np++) {
                uint32_t off = (uint32_t)((n0 + np * 16 + b_nrow) * GEMM_ROWB + (ks * 16 + b_kh) * 2);
                uint32_t b0, b1, b2, b3;
                LDSM4(b0, b1, b2, b3, bB + off);
#pragma unroll
                for (int mt = 0; mt < 2; mt++) {
                    MMA16816H(acc[mt][np * 2], ahb[cur][mt], b0, b1);
                    MMA16816H(acc[mt][np * 2], alb[cur][mt], b0, b1);
                    MMA16816H(acc[mt][np * 2 + 1], ahb[cur][mt], b2, b3);
                    MMA16816H(acc[mt][np * 2 + 1], alb[cur][mt], b2, b3);
                }
            }
        }
        __syncthreads();
    }
#undef LOAD_STAGE
#undef LOAD_A

    const int er = lane >> 2;
    const int ec = (lane & 3) * 2;
#pragma unroll
    for (int mt = 0; mt < 2; mt++) {
#pragma unroll
        for (int nt = 0; nt < 8; nt++) {
            size_t row = arow0 + m0 + mt * 16 + er;
            size_t col = brow0 + n0 + nt * 8 + ec;
            float2 v0 = make_float2(acc[mt][nt][0], acc[mt][nt][1]);
            float2 v1 = make_float2(acc[mt][nt][2], acc[mt][nt][3]);
            *reinterpret_cast<float2*>(Cout + row * 1024 + col) = v0;
            *reinterpret_cast<float2*>(Cout + (row + 8) * 1024 + col) = v1;
        }
    }
}

// ---------------- split x to fp16 hi/lo ----------------
__global__ __launch_bounds__(256) void splitx_kernel(const float* __restrict__ x)
{
    const int i0 = (blockIdx.x * 256 + threadIdx.x) * 4;
    float4 v = *reinterpret_cast<const float4*>(x + i0);
    float vv[4];
    vv[0] = v.x; vv[1] = v.y; vv[2] = v.z; vv[3] = v.w;
    for (int j = 0; j < 4; j++) {
        __half hb = __float2half_rn(vv[j]);
        d_xh[i0 + j] = hb;
        d_xl[i0 + j] = __float2half_rn(vv[j] - __half2float(hb));
    }
}

// ---------------- transpose weights: [K][N] f32 -> [N][K] fp16 ----------------
__global__ void wsplit_kernel(
    const float* __restrict__ Wq, const float* __restrict__ Wk, const float* __restrict__ Wv,
    const float* __restrict__ Wg, const float* __restrict__ Wo)
{
    __shared__ float ts[32][33];
    const int z = blockIdx.z;
    const float* W = (z == 0) ? Wq : (z == 1) ? Wk : (z == 2) ? Wv : (z == 3) ? Wg : Wo;
    const int n0 = blockIdx.x * 32, k0 = blockIdx.y * 32;
    const int txx = threadIdx.x, tyy = threadIdx.y;
    for (int j = 0; j < 4; j++)
        ts[tyy + 8 * j][txx] = W[(size_t)(k0 + tyy + 8 * j) * 1024 + n0 + txx];
    __syncthreads();
    __half* ot = d_Wt + (size_t)z * 1048576;
    for (int j = 0; j < 4; j++) {
        float v = ts[txx][tyy + 8 * j];
        size_t idx = (size_t)(n0 + tyy + 8 * j) * 1024 + k0 + txx;
        ot[idx] = __float2half_rn(v);
    }
}

// ---------------- conv + silu + relayout (4 t per thread) ----------------
__global__ __launch_bounds__(256) void conv_silu_kernel(
    const float* __restrict__ wq, const float* __restrict__ wk, const float* __restrict__ wv)
{
    const int which = blockIdx.z;
    const int idx = blockIdx.x * 256 + threadIdx.x;
    const int c = idx & (C - 1);
    const int bt4 = idx >> 10;
    const int t4 = bt4 & (T / 4 - 1);
    const int b = bt4 >> 9;
    const int t0 = t4 * 4;

    const float* src = which == 0 ? d_qpre : which == 1 ? d_kpre : d_vpre;
    const float* w = which == 0 ? wq : which == 1 ? wk : wv;
    float* dst = which == 0 ? d_q : which == 1 ? d_k : d_v;

    float4 w4 = *reinterpret_cast<const float4*>(w + c * 4);
    float wr[4];
    wr[0] = w4.x; wr[1] = w4.y; wr[2] = w4.z; wr[3] = w4.w;

    const float* srow = src + (size_t)(b * T) * C + c;
    float xv[7];
    for (int j = 0; j < 7; j++) {
        int tt = t0 - 3 + j;
        xv[j] = (tt >= 0) ? srow[(size_t)tt * C] : 0.f;
    }

    const int h = c >> 6, dk = c & 63;
    float* drow = dst + (((size_t)(b * H + h)) * T + t0) * DK + dk;
    for (int k = 0; k < 4; k++) {
        float acc = 0.f;
        for (int j = 0; j < 4; j++) acc = fmaf(xv[k + j], wr[j], acc);
        drow[(size_t)k * DK] = siluf(acc);
    }
}

// ---------------- l2 norm ----------------
__global__ __launch_bounds__(256) void l2norm_kernel()
{
    const int row = blockIdx.x * 8 + (threadIdx.x >> 5);
    const int lane = threadIdx.x & 31;
    {
        float2 qv = *reinterpret_cast<const float2*>(d_q + (size_t)row * 64 + lane * 2);
        float ss = qv.x * qv.x + qv.y * qv.y;
        for (int o = 16; o; o >>= 1) ss += __shfl_xor_sync(0xffffffffu, ss, o);
        float r = rsqrtf(ss + 1e-6f) * 0.125f;
        qv.x *= r; qv.y *= r;
        *reinterpret_cast<float2*>(d_q + (size_t)row * 64 + lane * 2) = qv;
    }
    {
        float2 kv = *reinterpret_cast<const float2*>(d_k + (size_t)row * 64 + lane * 2);
        float ss = kv.x * kv.x + kv.y * kv.y;
        for (int o = 16; o; o >>= 1) ss += __shfl_xor_sync(0xffffffffu, ss, o);
        float r = rsqrtf(ss + 1e-6f);
        kv.x *= r; kv.y *= r;
        *reinterpret_cast<float2*>(d_k + (size_t)row * 64 + lane * 2) = kv;
    }
}

// ---------------- g/beta as tiled small GEMM ----------------
__global__ __launch_bounds__(256) void gbeta2_kernel(
    const float* __restrict__ x, const float* __restrict__ Wa, const float* __restrict__ Wb,
    const float* __restrict__ A_log, const float* __restrict__ dt_bias)
{
    __shared__ float xs[64][33];
    __shared__ float ws[32][32];
    const int row0 = blockIdx.x * 64;
    const int tid = threadIdx.x;
    const int cc = tid & 31, rr = tid >> 5;

    float acc[8];
    for (int i = 0; i < 8; i++) acc[i] = 0.f;

    for (int k0 = 0; k0 < 1024; k0 += 32) {
        {
            int r = tid >> 3, c4 = (tid & 7) * 4;
            for (int pp = 0; pp < 2; pp++) {
                float4 v = *reinterpret_cast<const float4*>(
                    x + (size_t)(row0 + r + pp * 32) * 1024 + k0 + c4);
                xs[r + pp * 32][c4] = v.x;
                xs[r + pp * 32][c4 + 1] = v.y;
                xs[r + pp * 32][c4 + 2] = v.z;
                xs[r + pp * 32][c4 + 3] = v.w;
            }
        }
        for (int i = 0; i < 4; i++) {
            int p = tid + i * 256;
            int kk = p >> 5, col = p & 31;
            ws[kk][col] = (col < 16) ? Wa[(size_t)(k0 + kk) * 16 + col]
                                     : Wb[(size_t)(k0 + kk) * 16 + col - 16];
        }
        __syncthreads();
        for (int i = 0; i < 8; i++) {
            const float* xr = &xs[rr + i * 8][0];
            float a = acc[i];
            for (int kk = 0; kk < 32; kk++) a = fmaf(xr[kk], ws[kk][cc], a);
            acc[i] = a;
        }
        __syncthreads();
    }

    for (int i = 0; i < 8; i++) {
        const int row = row0 + rr + i * 8;
        const int b = row >> 11, t = row & 2047;
        if (cc < 16) {
            const int h = cc;
            float zz = acc[i] + dt_bias[h];
            float sp = (zz > 20.f) ? zz : log1pf(expf(zz));
            d_g[(size_t)(b * H + h) * T + t] = -expf(A_log[h]) * sp;
        } else {
            const int h = cc - 16;
            d_beta[(size_t)(b * H + h) * T + t] = 1.f / (1.f + expf(-acc[i]));
        }
    }
}

// ================= chunked delta rule =================
// phaseA: no Kt (row-dot P3 against Ks), barrier-free substitution, shfl-scan cumsum.
#define PA 68
__global__ __launch_bounds__(256) void phaseA_kernel()
{
    extern __shared__ float smA[];
    float* Ks = smA;
    float* Qs = Ks + 64 * PA;
    float* U0 = Qs + 64 * PA;
    float* Ws = U0 + 64 * PA;
    float* Ms = Ws + 64 * PA;
    float* cs = Ms + 64 * PA;
    float* es = cs + 64;
    float* bv = es + 64;
    float* gv = bv + 64;

    const int unit = blockIdx.x;
    const int chunk = unit & (NC - 1);
    const int bh = unit >> 5;
    const int tid = threadIdx.x;
    const int t0 = chunk * 64;
    const int tx = tid & 15, ty = tid >> 4;

    const float* qg = d_q + ((size_t)bh * T + t0) * DK;
    const float* kg = d_k + ((size_t)bh * T + t0) * DK;
    const float* vg = d_v + ((size_t)bh * T + t0) * DK;

#pragma unroll
    for (int i = 0; i < 4; i++) {
        int p = tid + i * 256;
        int r = p >> 4, c4 = (p & 15) * 4;
        *reinterpret_cast<float4*>(Ks + r * PA + c4) = *reinterpret_cast<const float4*>(kg + r * 64 + c4);
        *reinterpret_cast<float4*>(Qs + r * PA + c4) = *reinterpret_cast<const float4*>(qg + r * 64 + c4);
        *reinterpret_cast<float4*>(U0 + r * PA + c4) = *reinterpret_cast<const float4*>(vg + r * 64 + c4);
    }
    if (tid < 64) {
        gv[tid] = d_g[(size_t)bh * T + t0 + tid];
        bv[tid] = d_beta[(size_t)bh * T + t0 + tid];
    }
    __syncthreads();
    // cumsum via 2-warp shfl scan
    if (tid < 64) {
        float v = gv[tid];
        for (int o = 1; o < 32; o <<= 1) {
            float n = __shfl_up_sync(0xffffffffu, v, o);
            if ((tid & 31) >= o) v += n;
        }
        cs[tid] = v;
    }
    __syncthreads();
    if (tid >= 32 && tid < 64) cs[tid] += cs[31];
    __syncthreads();
    if (tid < 64) {
        es[tid] = expf(cs[tid]);
        gv[tid] = expf(cs[63] - cs[tid]);
    }
    __syncthreads();
#pragma unroll
    for (int i = 0; i < 16; i++) {
        int p = tid + i * 256;
        int r = p >> 6, ccx = p & 63;
        float kvv = Ks[r * PA + ccx];
        Ws[r * PA + ccx] = bv[r] * es[r] * kvv;
        U0[r * PA + ccx] *= bv[r];
    }
    __syncthreads();

    // P1: acc[i][j] = sum_d A[ty4+i][d] * B[d][tx4+j]   (B direct)
#define P1(Aptr, Bptr)                                                            \
    {                                                                             \
        _Pragma("unroll")                                                         \
        for (int i = 0; i < 4; i++)                                               \
            _Pragma("unroll")                                                     \
            for (int j = 0; j < 4; j++) acc[i][j] = 0.f;                          \
        for (int d4 = 0; d4 < 16; d4++) {                                         \
            float4 av[4];                                                         \
            _Pragma("unroll")                                                     \
            for (int i = 0; i < 4; i++)                                           \
                av[i] = *reinterpret_cast<const float4*>((Aptr) + (ty * 4 + i) * PA + d4 * 4); \
            const float* ap = reinterpret_cast<const float*>(av);                 \
            _Pragma("unroll")                                                     \
            for (int u = 0; u < 4; u++) {                                         \
                float4 rb = *reinterpret_cast<const float4*>((Bptr) + (d4 * 4 + u) * PA + tx * 4); \
                _Pragma("unroll")                                                 \
                for (int i = 0; i < 4; i++) {                                     \
                    float a = ap[i * 4 + u];                                      \
                    acc[i][0] = fmaf(a, rb.x, acc[i][0]);                         \
                    acc[i][1] = fmaf(a, rb.y, acc[i][1]);                         \
                    acc[i][2] = fmaf(a, rb.z, acc[i][2]);                         \
                    acc[i][3] = fmaf(a, rb.w, acc[i][3]);                         \
                }                                                                 \
            }                                                                     \
        }                                                                         \
    }
    // P2: acc[i][j] = sum_s A[s][ty4+i] * B[s][tx4+j]
#define P2(Aptr, Bptr)                                                            \
    {                                                                             \
        _Pragma("unroll")                                                         \
        for (int i = 0; i < 4; i++)                                               \
            _Pragma("unroll")                                                     \
            for (int j = 0; j < 4; j++) acc[i][j] = 0.f;                          \
        for (int s = 0; s < 64; s++) {                                            \
            float4 ra = *reinterpret_cast<const float4*>((Aptr) + s * PA + ty * 4); \
            float4 rb = *reinterpret_cast<const float4*>((Bptr) + s * PA + tx * 4); \
            const float* rap = reinterpret_cast<const float*>(&ra);               \
            _Pragma("unroll")                                                     \
            for (int i = 0; i < 4; i++) {                                         \
                float a = rap[i];                                                 \
                acc[i][0] = fmaf(a, rb.x, acc[i][0]);                             \
                acc[i][1] = fmaf(a, rb.y, acc[i][1]);                             \
                acc[i][2] = fmaf(a, rb.z, acc[i][2]);                             \
                acc[i][3] = fmaf(a, rb.w, acc[i][3]);                             \
            }                                                                     \
        }                                                                         \
    }
    // P3: acc[i][j] = sum_d A[ty4+i][d] * B[tx4+j][d]   (row-dot; replaces Kt)
#define P3(Aptr, Bptr)                                                            \
    {                                                                             \
        _Pragma("unroll")                                                         \
        for (int i = 0; i < 4; i++)                                               \
            _Pragma("unroll")                                                     \
            for (int j = 0; j < 4; j++) acc[i][j] = 0.f;                          \
        for (int d4 = 0; d4 < 16; d4++) {                                         \
            float4 av[4], bw[4];                                                  \
            _Pragma("unroll")                                                     \
            for (int i = 0; i < 4; i++)                                           \
                av[i] = *reinterpret_cast<const float4*>((Aptr) + (ty * 4 + i) * PA + d4 * 4); \
            _Pragma("unroll")                                                     \
            for (int j = 0; j < 4; j++)                                           \
                bw[j] = *reinterpret_cast<const float4*>((Bptr) + (tx * 4 + j) * PA + d4 * 4); \
            const float* ap = reinterpret_cast<const float*>(av);                 \
            const float* bp = reinterpret_cast<const float*>(bw);                 \
            _Pragma("unroll")                                                     \
            for (int i = 0; i < 4; i++)                                           \
                _Pragma("unroll")                                                 \
                for (int j = 0; j < 4; j++) {                                     \
                    float s0 = acc[i][j];                                         \
                    s0 = fmaf(ap[i * 4 + 0], bp[j * 4 + 0], s0);                  \
                    s0 = fmaf(ap[i * 4 + 1], bp[j * 4 + 1], s0);                  \
                    s0 = fmaf(ap[i * 4 + 2], bp[j * 4 + 2], s0);                  \
                    s0 = fmaf(ap[i * 4 + 3], bp[j * 4 + 3], s0);                  \
                    acc[i][j] = s0;                                               \
                }                                                                 \
        }                                                                         \
    }

    float acc[4][4];

    // M = strict_lower(beta_t e^{c_t-c_s} (k_t . k_s))
    P3(Ks, Ks);
#pragma unroll
    for (int i = 0; i < 4; i++) {
        int t = ty * 4 + i;
#pragma unroll
        for (int j = 0; j < 4; j++) {
            int s = tx * 4 + j;
            Ms[t * PA + s] = (t > s) ? bv[t] * expf(cs[t] - cs[s]) * acc[i][j] : 0.f;
        }
    }
    __syncthreads();

    // barrier-free forward substitution: thread owns one column of U0 or Ws
    if (tid < 128) {
        const int j = tid & 63;
        float* X = (tid < 64) ? U0 : Ws;
        for (int t = 1; t < 64; t++) {
            const float* mrow = Ms + t * PA;
            float a0 = 0.f, a1 = 0.f, a2 = 0.f, a3 = 0.f;
            int s = 0;
            for (; s + 4 <= t; s += 4) {
                a0 = fmaf(mrow[s],     X[s * PA + j],       a0);
                a1 = fmaf(mrow[s + 1], X[(s + 1) * PA + j], a1);
                a2 = fmaf(mrow[s + 2], X[(s + 2) * PA + j], a2);
                a3 = fmaf(mrow[s + 3], X[(s + 3) * PA + j], a3);
            }
            for (; s < t; s++) a0 = fmaf(mrow[s], X[s * PA + j], a0);
            X[t * PA + j] -= (a0 + a1) + (a2 + a3);
        }
    }
    __syncthreads();

    // Aqk = lower_incl(e^{c_t-c_s} (q_t.k_s)) -> Ms ; then scale Ks rows by e^{cC-c_s}
    P3(Qs, Ks);
#pragma unroll
    for (int i = 0; i < 4; i++) {
        int t = ty * 4 + i;
#pragma unroll
        for (int j = 0; j < 4; j++) {
            int s = tx * 4 + j;
            Ms[t * PA + s] = (t >= s) ? expf(cs[t] - cs[s]) * acc[i][j] : 0.f;
        }
    }
#pragma unroll
    for (int i = 0; i < 16; i++) {
        int p = tid + i * 256;
        int r = p >> 6, ccx = p & 63;
        Ks[r * PA + ccx] *= gv[r];
    }
    __syncthreads();

    float* oOi = d_Oi + (size_t)unit * 4096;
    float* oQe = d_Qe + (size_t)unit * 4096;
    float* oSm = d_Sm + (size_t)unit * 4096;
    float* oSa = d_Sa + (size_t)unit * 4096;

    P1(Ms, U0);
#pragma unroll
    for (int i = 0; i < 4; i++)
        *reinterpret_cast<float4*>(oOi + (ty * 4 + i) * 64 + tx * 4) =
            make_float4(acc[i][0], acc[i][1], acc[i][2], acc[i][3]);

    P1(Ms, Ws);
#pragma unroll
    for (int i = 0; i < 4; i++) {
        int t = ty * 4 + i;
        float4 q4 = *reinterpret_cast<const float4*>(Qs + t * PA + tx * 4);
        float e = es[t];
        *reinterpret_cast<float4*>(oQe + t * 64 + tx * 4) =
            make_float4(e * q4.x - acc[i][0], e * q4.y - acc[i][1],
                        e * q4.z - acc[i][2], e * q4.w - acc[i][3]);
    }

    P2(Ks, Ws);
    {
        float ecc = es[63];
#pragma unroll
        for (int i = 0; i < 4; i++) {
            int a = ty * 4 + i;
            float4 v4;
            v4.x = ((a == tx * 4 + 0) ? ecc : 0.f) - acc[i][0];
            v4.y = ((a == tx * 4 + 1) ? ecc : 0.f) - acc[i][1];
            v4.z = ((a == tx * 4 + 2) ? ecc : 0.f) - acc[i][2];
            v4.w = ((a == tx * 4 + 3) ? ecc : 0.f) - acc[i][3];
            *reinterpret_cast<float4*>(oSm + a * 64 + tx * 4) = v4;
        }
    }
    P2(Ks, U0);
#pragma unroll
    for (int i = 0; i < 4; i++)
        *reinterpret_cast<float4*>(oSa + (ty * 4 + i) * 64 + tx * 4) =
            make_float4(acc[i][0], acc[i][1], acc[i][2], acc[i][3]);
#undef P1
#undef P2
#undef P3
}

#define PB 68
#define PS 36
__global__ __launch_bounds__(256) void phaseB_kernel()
{
    extern __shared__ float smB[];
    float* Qe = smB;
    float* Sm = Qe + 64 * PB;
    float* Sbuf0 = Sm + 64 * PB;
    float* Sbuf1 = Sbuf0 + 64 * PS;

    const int bh = blockIdx.x >> 1;
    const int half = blockIdx.x & 1;
    const int b = bh >> 4, h = bh & 15;
    const int tid = threadIdx.x;
    const int tx = tid & 7, ty = tid >> 3;

    for (int i = tid; i < 64 * PS * 2; i += 256) Sbuf0[i] = 0.f;
    __syncthreads();

    float* Sc = Sbuf0;
    float* Sn = Sbuf1;

    for (int c = 0; c < NC; c++) {
        const int unit = bh * NC + c;
        const float* qe_g = d_Qe + (size_t)unit * 4096;
        const float* sm_g = d_Sm + (size_t)unit * 4096;
#pragma unroll
        for (int i = 0; i < 4; i++) {
            int p = tid + i * 256;
            int r = p >> 4, c4 = (p & 15) * 4;
            *reinterpret_cast<float4*>(Qe + r * PB + c4) = *reinterpret_cast<const float4*>(qe_g + r * 64 + c4);
            *reinterpret_cast<float4*>(Sm + r * PB + c4) = *reinterpret_cast<const float4*>(sm_g + r * 64 + c4);
        }
        __syncthreads();

        const float* oi_g = d_Oi + (size_t)unit * 4096 + half * 32;
        const float* sa_g = d_Sa + (size_t)unit * 4096 + half * 32;
        const int r0 = ty * 2, r1 = ty * 2 + 1;

        float4 o0 = *reinterpret_cast<const float4*>(oi_g + r0 * 64 + tx * 4);
        float4 o1 = *reinterpret_cast<const float4*>(oi_g + r1 * 64 + tx * 4);
        float4 s0 = *reinterpret_cast<const float4*>(sa_g + r0 * 64 + tx * 4);
        float4 s1 = *reinterpret_cast<const float4*>(sa_g + r1 * 64 + tx * 4);

        for (int d = 0; d < 64; d++) {
            float4 rb = *reinterpret_cast<const float4*>(Sc + d * PS + tx * 4);
            float a0 = Qe[r0 * PB + d], a1 = Qe[r1 * PB + d];
            float m0 = Sm[r0 * PB + d], m1 = Sm[r1 * PB + d];
            o0.x = fmaf(a0, rb.x, o0.x); o0.y = fmaf(a0, rb.y, o0.y);
            o0.z = fmaf(a0, rb.z, o0.z); o0.w = fmaf(a0, rb.w, o0.w);
            o1.x = fmaf(a1, rb.x, o1.x); o1.y = fmaf(a1, rb.y, o1.y);
            o1.z = fmaf(a1, rb.z, o1.z); o1.w = fmaf(a1, rb.w, o1.w);
            s0.x = fmaf(m0, rb.x, s0.x); s0.y = fmaf(m0, rb.y, s0.y);
            s0.z = fmaf(m0, rb.z, s0.z); s0.w = fmaf(m0, rb.w, s0.w);
            s1.x = fmaf(m1, rb.x, s1.x); s1.y = fmaf(m1, rb.y, s1.y);
            s1.z = fmaf(m1, rb.z, s1.z); s1.w = fmaf(m1, rb.w, s1.w);
        }

        *reinterpret_cast<float4*>(d_o + (((size_t)(b * T + c * 64 + r0) * H + h) * 64 + half * 32 + tx * 4)) = o0;
        *reinterpret_cast<float4*>(d_o + (((size_t)(b * T + c * 64 + r1) * H + h) * 64 + half * 32 + tx * 4)) = o1;
        *reinterpret_cast<float4*>(Sn + r0 * PS + tx * 4) = s0;
        *reinterpret_cast<float4*>(Sn + r1 * PS + tx * 4) = s1;
        __syncthreads();
        float* tmp = Sc; Sc = Sn; Sn = tmp;
    }
}

// ---------------- gated RMSNorm -> fp16 hi/lo ----------------
__global__ __launch_bounds__(256) void rmsgate_kernel(const float* __restrict__ rms_w)
{
    const int row = blockIdx.x * 8 + (threadIdx.x >> 5);
    const int lane = threadIdx.x & 31;
    const float* orow = d_o + (size_t)row * 64;
    float2 ov = *reinterpret_cast<const float2*>(orow + lane * 2);
    float ss = ov.x * ov.x + ov.y * ov.y;
    for (int o = 16; o; o >>= 1) ss += __shfl_xor_sync(0xffffffffu, ss, o);
    const float r = rsqrtf(ss * (1.f / 64.f) + 1e-5f);

    const int bt = row >> 4, h = row & 15;
    float2 gv = *reinterpret_cast<const float2*>(d_gpre + (size_t)bt * C + h * 64 + lane * 2);
    float2 wv = *reinterpret_cast<const float2*>(rms_w + lane * 2);

    float rx = ov.x * r * wv.x * siluf(gv.x);
    float ry = ov.y * r * wv.y * siluf(gv.y);

    const size_t oidx = (size_t)bt * C + h * 64 + lane * 2;
    __half hx = __float2half_rn(rx);
    __half hy = __float2half_rn(ry);
    d_ogh[oidx] = hx;
    d_ogh[oidx + 1] = hy;
    d_ogl[oidx] = __float2half_rn(rx - __half2float(hx));
    d_ogl[oidx + 1] = __float2half_rn(ry - __half2float(hy));
}

// ---------------- launch ----------------
extern "C" void kernel_launch(void* const* d_in, const int* in_sizes, int n_in,
                              void* d_out, int out_size)
{
    const float* x       = (const float*)d_in[0];
    const float* Wq      = (const float*)d_in[1];
    const float* Wk      = (const float*)d_in[2];
    const float* Wv      = (const float*)d_in[3];
    const float* Wa      = (const float*)d_in[4];
    const float* Wb      = (const float*)d_in[5];
    const float* Wg      = (const float*)d_in[6];
    const float* Wo      = (const float*)d_in[7];
    const float* conv_q  = (const float*)d_in[8];
    const float* conv_k  = (const float*)d_in[9];
    const float* conv_v  = (const float*)d_in[10];
    const float* A_log   = (const float*)d_in[11];
    const float* dt_bias = (const float*)d_in[12];
    const float* rms_w   = (const float*)d_in[13];
    float* out = (float*)d_out;

    float *qpre, *kpre, *vpre, *gpre;
    __half *xh, *xl, *wt, *ogh, *ogl;
    cudaGetSymbolAddress((void**)&qpre, d_qpre);
    cudaGetSymbolAddress((void**)&kpre, d_kpre);
    cudaGetSymbolAddress((void**)&vpre, d_vpre);
    cudaGetSymbolAddress((void**)&gpre, d_gpre);
    cudaGetSymbolAddress((void**)&xh, d_xh);
    cudaGetSymbolAddress((void**)&xl, d_xl);
    cudaGetSymbolAddress((void**)&wt, d_Wt);
    cudaGetSymbolAddress((void**)&ogh, d_ogh);
    cudaGetSymbolAddress((void**)&ogl, d_ogl);

    const int smemA = (5 * 64 * PA + 4 * 64) * 4;
    const int smemB = (2 * 64 * PB + 2 * 64 * PS) * 4;
    cudaFuncSetAttribute(phaseA_kernel, cudaFuncAttributeMaxDynamicSharedMemorySize, smemA);
    cudaFuncSetAttribute(phaseB_kernel, cudaFuncAttributeMaxDynamicSharedMemorySize, smemB);
    cudaFuncSetAttribute(gemm_mma_kernel, cudaFuncAttributeMaxDynamicSharedMemorySize, GSMEM_BYTES);

    // 0) operand prep
    splitx_kernel<<<BT * D / 1024, 256>>>(x);
    wsplit_kernel<<<dim3(32, 32, 5), dim3(32, 8)>>>(Wq, Wk, Wv, Wg, Wo);

    // 1) projections q,k,v,g (mma.sync fp16x2, 2-stage, 2 CTA/SM)
    gemm_mma_kernel<<<dim3(8, 32, 4), 256, GSMEM_BYTES>>>(
        xh, xl, wt, qpre, kpre, vpre, gpre);

    // 2) conv + silu + relayout
    conv_silu_kernel<<<dim3(BT * C / 1024, 1, 3), 256>>>(conv_q, conv_k, conv_v);

    // 3) l2 norm
    l2norm_kernel<<<B * H * T / 8, 256>>>();

    // 4) g, beta
    gbeta2_kernel<<<BT / 64, 256>>>(x, Wa, Wb, A_log, dt_bias);

    // 5) chunked delta rule
    phaseA_kernel<<<UNITS, 256, smemA>>>();
    phaseB_kernel<<<B * H * 2, 256, smemB>>>();

    // 6) gated RMS norm (+ fp16 split)
    rmsgate_kernel<<<BT * H / 8, 256>>>(rms_w);

    // 7) output projection
    gemm_mma_kernel<<<dim3(8, 32, 1), 256, GSMEM_BYTES>>>(
        ogh, ogl, wt + 4ull * 1048576, out, out, out, out);
}

// round 16
// speedup vs baseline: 1.0794x; 1.0517x over previous
#include <cuda_runtime.h>
#include <cuda_fp16.h>
#include <cstdint>
#include <math.h>

namespace {
constexpr int B  = 2;
constexpr int T  = 2048;
constexpr int D  = 1024;
constexpr int H  = 16;
constexpr int DK = 64;
constexpr int BT = B * T;
constexpr int C  = H * DK;
constexpr int NC = T / 64;
constexpr int UNITS = B * H * NC;   // 1024
}

// ---------------- scratch ----------------
__device__ float d_qpre[BT * C];
__device__ float d_kpre[BT * C];
__device__ float d_vpre[BT * C];
__device__ float d_gpre[BT * C];
__device__ float d_q[B * H * T * DK];
__device__ float d_k[B * H * T * DK];
__device__ float d_v[B * H * T * DK];
__device__ float d_g[B * H * T];
__device__ float d_beta[B * H * T];
__device__ float d_o[BT * C];
__device__ float d_Oi[UNITS * 4096];
__device__ float d_Qe[UNITS * 4096];
__device__ float d_Sm[UNITS * 4096];
__device__ float d_Sa[UNITS * 4096];
__device__ __half d_xh[BT * D];
__device__ __half d_xl[BT * D];
__device__ __half d_Wt[5 * 1024 * 1024];   // [z][N][K] transposed weights, single fp16
__device__ __half d_ogh[BT * C];
__device__ __half d_ogl[BT * C];

__device__ __forceinline__ float siluf(float x) { return x / (1.f + expf(-x)); }

__device__ __forceinline__ uint32_t smem_to_u32(const void* smem_ptr) {
    uint32_t addr;
    asm("{ .reg .u64 tmp; cvta.to.shared.u64 tmp, %1; cvt.u32.u64 %0, tmp; }"
        : "=r"(addr) : "l"(smem_ptr));
    return addr;
}
__device__ __forceinline__ void cp16s(uint32_t saddr, const void* g) {
    asm volatile("cp.async.cg.shared.global [%0], [%1], 16;" :: "r"(saddr), "l"(g));
}
__device__ __forceinline__ void cp_commit() {
    asm volatile("cp.async.commit_group;");
}
__device__ __forceinline__ void cp_wait1() {
    asm volatile("cp.async.wait_group 1;" ::: "memory");
}
__device__ __forceinline__ void cp_wait0() {
    asm volatile("cp.async.wait_group 0;" ::: "memory");
}

#define LDSM4(r0, r1, r2, r3, addr) \
    asm volatile("ldmatrix.sync.aligned.m8n8.x4.shared.b16 {%0, %1, %2, %3}, [%4];" \
                 : "=r"(r0), "=r"(r1), "=r"(r2), "=r"(r3) : "r"(addr))

#define MMA16816H(d, a, bb0, bb1) \
    asm volatile("mma.sync.aligned.m16n8k16.row.col.f32.f16.f16.f32 " \
                 "{%0, %1, %2, %3}, {%4, %5, %6, %7}, {%8, %9}, {%0, %1, %2, %3};" \
                 : "+f"((d)[0]), "+f"((d)[1]), "+f"((d)[2]), "+f"((d)[3]) \
                 : "r"((a)[0]), "r"((a)[1]), "r"((a)[2]), "r"((a)[3]), \
                   "r"(bb0), "r"(bb1))

// ================= mma.sync fp16x2 GEMM, 128x128 tile, 2-stage, 2 CTA/SM =================
#define GEMM_ROWB 144
#define GEMM_TEN  (128 * GEMM_ROWB)            // 18432 B per tensor
#define GEMM_STAGE (3 * GEMM_TEN)              // Ah|Al|B = 55296 B
#define GSMEM_BYTES (2 * GEMM_STAGE)           // 110592 B

__global__ __launch_bounds__(256, 2) void gemm_mma_kernel(
    const __half* __restrict__ Ah, const __half* __restrict__ Al,
    const __half* __restrict__ Wt,
    float* __restrict__ C0, float* __restrict__ C1,
    float* __restrict__ C2, float* __restrict__ C3)
{
    extern __shared__ unsigned char gsm[];
    const uint32_t sbase = smem_to_u32(gsm);

    const int tid = threadIdx.x;
    const int wid = tid >> 5;
    const int lane = tid & 31;
    const int z = blockIdx.z;

    const __half* Bw = Wt + (size_t)z * 1048576;
    float* Cout = (z == 0) ? C0 : (z == 1) ? C1 : (z == 2) ? C2 : C3;

    const size_t arow0 = (size_t)blockIdx.y * 128;
    const size_t brow0 = (size_t)blockIdx.x * 128;

    const int wm = wid >> 1;
    const int wn = wid & 1;
    const int m0 = wm * 32;
    const int n0 = wn * 64;

    const int a_row  = (lane & 7) + ((lane >> 3) & 1) * 8;
    const int a_colh = (lane >> 4) * 8;
    const int b_nrow = (lane & 7) + (lane >> 4) * 8;
    const int b_kh   = ((lane >> 3) & 1) * 8;

    float acc[2][8][4];
#pragma unroll
    for (int mt = 0; mt < 2; mt++)
#pragma unroll
        for (int nt = 0; nt < 8; nt++)
#pragma unroll
            for (int e = 0; e < 4; e++) acc[mt][nt][e] = 0.f;

#define LOAD_STAGE(chunk_i, stage_i) do {                                        \
        const int koff_ = (chunk_i) * 64;                                        \
        const uint32_t stb_ = sbase + (stage_i) * GEMM_STAGE;                    \
        for (int i_ = 0; i_ < 12; i_++) {                                        \
            int p_ = tid + i_ * 256;                                             \
            int sel_ = p_ >> 10;                                                 \
            int q_ = p_ & 1023;                                                  \
            int r_ = q_ >> 3;                                                    \
            int e_ = q_ & 7;                                                     \
            const __half* src_ = (sel_ == 0) ? Ah : (sel_ == 1) ? Al : Bw;       \
            size_t row_ = ((sel_ < 2) ? arow0 : brow0) + r_;                     \
            uint32_t dsm_ = stb_ + sel_ * GEMM_TEN + r_ * GEMM_ROWB + e_ * 16;   \
            cp16s(dsm_, src_ + row_ * 1024 + koff_ + e_ * 8);                    \
        }                                                                        \
        cp_commit();                                                             \
    } while (0)

#define LOAD_A(ks_, bf_) do {                                                     \
        _Pragma("unroll")                                                         \
        for (int mt_ = 0; mt_ < 2; mt_++) {                                       \
            uint32_t off_ = (uint32_t)((m0 + mt_ * 16 + a_row) * GEMM_ROWB        \
                                       + ((ks_) * 16 + a_colh) * 2);              \
            LDSM4(ahb[bf_][mt_][0], ahb[bf_][mt_][1], ahb[bf_][mt_][2],           \
                  ahb[bf_][mt_][3], bAh + off_);                                  \
            LDSM4(alb[bf_][mt_][0], alb[bf_][mt_][1], alb[bf_][mt_][2],           \
                  alb[bf_][mt_][3], bAl + off_);                                  \
        }                                                                         \
    } while (0)

    LOAD_STAGE(0, 0);

    for (int c = 0; c < 16; c++) {
        if (c + 1 < 16) {
            LOAD_STAGE(c + 1, (c + 1) & 1);
            cp_wait1();
        } else {
            cp_wait0();
        }
        __syncthreads();

        const uint32_t stb = sbase + (c & 1) * GEMM_STAGE;
        const uint32_t bAh = stb;
        const uint32_t bAl = stb + GEMM_TEN;
        const uint32_t bB  = stb + 2 * GEMM_TEN;

        uint32_t ahb[2][2][4], alb[2][2][4];
        LOAD_A(0, 0);

#pragma unroll
        for (int ks = 0; ks < 4; ks++) {
            const int cur = ks & 1;
            const int nxt = cur ^ 1;
            if (ks < 3) LOAD_A(ks + 1, nxt);

#pragma unroll
            for (int np = 0; np < 4; np++) {
                uint32_t off = (uint32_t)((n0 + np * 16 + b_nrow) * GEMM_ROWB + (ks * 16 + b_kh) * 2);
                uint32_t b0, b1, b2, b3;
                LDSM4(b0, b1, b2, b3, bB + off);
#pragma unroll
                for (int mt = 0; mt < 2; mt++) {
                    MMA16816H(acc[mt][np * 2], ahb[cur][mt], b0, b1);
                    MMA16816H(acc[mt][np * 2], alb[cur][mt], b0, b1);
                    MMA16816H(acc[mt][np * 2 + 1], ahb[cur][mt], b2, b3);
                    MMA16816H(acc[mt][np * 2 + 1], alb[cur][mt], b2, b3);
                }
            }
        }
        __syncthreads();
    }
#undef LOAD_STAGE
#undef LOAD_A

    const int er = lane >> 2;
    const int ec = (lane & 3) * 2;
#pragma unroll
    for (int mt = 0; mt < 2; mt++) {
#pragma unroll
        for (int nt = 0; nt < 8; nt++) {
            size_t row = arow0 + m0 + mt * 16 + er;
            size_t col = brow0 + n0 + nt * 8 + ec;
            float2 v0 = make_float2(acc[mt][nt][0], acc[mt][nt][1]);
            float2 v1 = make_float2(acc[mt][nt][2], acc[mt][nt][3]);
            *reinterpret_cast<float2*>(Cout + row * 1024 + col) = v0;
            *reinterpret_cast<float2*>(Cout + (row + 8) * 1024 + col) = v1;
        }
    }
}

// ---------------- split x to fp16 hi/lo ----------------
__global__ __launch_bounds__(256) void splitx_kernel(const float* __restrict__ x)
{
    const int i0 = (blockIdx.x * 256 + threadIdx.x) * 4;
    float4 v = *reinterpret_cast<const float4*>(x + i0);
    float vv[4];
    vv[0] = v.x; vv[1] = v.y; vv[2] = v.z; vv[3] = v.w;
    for (int j = 0; j < 4; j++) {
        __half hb = __float2half_rn(vv[j]);
        d_xh[i0 + j] = hb;
        d_xl[i0 + j] = __float2half_rn(vv[j] - __half2float(hb));
    }
}

// ---------------- transpose weights: [K][N] f32 -> [N][K] fp16 ----------------
__global__ void wsplit_kernel(
    const float* __restrict__ Wq, const float* __restrict__ Wk, const float* __restrict__ Wv,
    const float* __restrict__ Wg, const float* __restrict__ Wo)
{
    __shared__ float ts[32][33];
    const int z = blockIdx.z;
    const float* W = (z == 0) ? Wq : (z == 1) ? Wk : (z == 2) ? Wv : (z == 3) ? Wg : Wo;
    const int n0 = blockIdx.x * 32, k0 = blockIdx.y * 32;
    const int txx = threadIdx.x, tyy = threadIdx.y;
    for (int j = 0; j < 4; j++)
        ts[tyy + 8 * j][txx] = W[(size_t)(k0 + tyy + 8 * j) * 1024 + n0 + txx];
    __syncthreads();
    __half* ot = d_Wt + (size_t)z * 1048576;
    for (int j = 0; j < 4; j++) {
        float v = ts[txx][tyy + 8 * j];
        size_t idx = (size_t)(n0 + tyy + 8 * j) * 1024 + k0 + txx;
        ot[idx] = __float2half_rn(v);
    }
}

// ---------------- conv + silu + relayout (4 t per thread) ----------------
__global__ __launch_bounds__(256) void conv_silu_kernel(
    const float* __restrict__ wq, const float* __restrict__ wk, const float* __restrict__ wv)
{
    const int which = blockIdx.z;
    const int idx = blockIdx.x * 256 + threadIdx.x;
    const int c = idx & (C - 1);
    const int bt4 = idx >> 10;
    const int t4 = bt4 & (T / 4 - 1);
    const int b = bt4 >> 9;
    const int t0 = t4 * 4;

    const float* src = which == 0 ? d_qpre : which == 1 ? d_kpre : d_vpre;
    const float* w = which == 0 ? wq : which == 1 ? wk : wv;
    float* dst = which == 0 ? d_q : which == 1 ? d_k : d_v;

    float4 w4 = *reinterpret_cast<const float4*>(w + c * 4);
    float wr[4];
    wr[0] = w4.x; wr[1] = w4.y; wr[2] = w4.z; wr[3] = w4.w;

    const float* srow = src + (size_t)(b * T) * C + c;
    float xv[7];
    for (int j = 0; j < 7; j++) {
        int tt = t0 - 3 + j;
        xv[j] = (tt >= 0) ? srow[(size_t)tt * C] : 0.f;
    }

    const int h = c >> 6, dk = c & 63;
    float* drow = dst + (((size_t)(b * H + h)) * T + t0) * DK + dk;
    for (int k = 0; k < 4; k++) {
        float acc = 0.f;
        for (int j = 0; j < 4; j++) acc = fmaf(xv[k + j], wr[j], acc);
        drow[(size_t)k * DK] = siluf(acc);
    }
}

// ---------------- l2 norm ----------------
__global__ __launch_bounds__(256) void l2norm_kernel()
{
    const int row = blockIdx.x * 8 + (threadIdx.x >> 5);
    const int lane = threadIdx.x & 31;
    {
        float2 qv = *reinterpret_cast<const float2*>(d_q + (size_t)row * 64 + lane * 2);
        float ss = qv.x * qv.x + qv.y * qv.y;
        for (int o = 16; o; o >>= 1) ss += __shfl_xor_sync(0xffffffffu, ss, o);
        float r = rsqrtf(ss + 1e-6f) * 0.125f;
        qv.x *= r; qv.y *= r;
        *reinterpret_cast<float2*>(d_q + (size_t)row * 64 + lane * 2) = qv;
    }
    {
        float2 kv = *reinterpret_cast<const float2*>(d_k + (size_t)row * 64 + lane * 2);
        float ss = kv.x * kv.x + kv.y * kv.y;
        for (int o = 16; o; o >>= 1) ss += __shfl_xor_sync(0xffffffffu, ss, o);
        float r = rsqrtf(ss + 1e-6f);
        kv.x *= r; kv.y *= r;
        *reinterpret_cast<float2*>(d_k + (size_t)row * 64 + lane * 2) = kv;
    }
}

// ---------------- g/beta as tiled small GEMM ----------------
__global__ __launch_bounds__(256) void gbeta2_kernel(
    const float* __restrict__ x, const float* __restrict__ Wa, const float* __restrict__ Wb,
    const float* __restrict__ A_log, const float* __restrict__ dt_bias)
{
    __shared__ float xs[64][33];
    __shared__ float ws[32][32];
    const int row0 = blockIdx.x * 64;
    const int tid = threadIdx.x;
    const int cc = tid & 31, rr = tid >> 5;

    float acc[8];
    for (int i = 0; i < 8; i++) acc[i] = 0.f;

    for (int k0 = 0; k0 < 1024; k0 += 32) {
        {
            int r = tid >> 3, c4 = (tid & 7) * 4;
            for (int pp = 0; pp < 2; pp++) {
                float4 v = *reinterpret_cast<const float4*>(
                    x + (size_t)(row0 + r + pp * 32) * 1024 + k0 + c4);
                xs[r + pp * 32][c4] = v.x;
                xs[r + pp * 32][c4 + 1] = v.y;
                xs[r + pp * 32][c4 + 2] = v.z;
                xs[r + pp * 32][c4 + 3] = v.w;
            }
        }
        for (int i = 0; i < 4; i++) {
            int p = tid + i * 256;
            int kk = p >> 5, col = p & 31;
            ws[kk][col] = (col < 16) ? Wa[(size_t)(k0 + kk) * 16 + col]
                                     : Wb[(size_t)(k0 + kk) * 16 + col - 16];
        }
        __syncthreads();
        for (int i = 0; i < 8; i++) {
            const float* xr = &xs[rr + i * 8][0];
            float a = acc[i];
            for (int kk = 0; kk < 32; kk++) a = fmaf(xr[kk], ws[kk][cc], a);
            acc[i] = a;
        }
        __syncthreads();
    }

    for (int i = 0; i < 8; i++) {
        const int row = row0 + rr + i * 8;
        const int b = row >> 11, t = row & 2047;
        if (cc < 16) {
            const int h = cc;
            float zz = acc[i] + dt_bias[h];
            float sp = (zz > 20.f) ? zz : log1pf(expf(zz));
            d_g[(size_t)(b * H + h) * T + t] = -expf(A_log[h]) * sp;
        } else {
            const int h = cc - 16;
            d_beta[(size_t)(b * H + h) * T + t] = 1.f / (1.f + expf(-acc[i]));
        }
    }
}

// ================= chunked delta rule =================
// phaseA: R11 structure (Kt transpose, P1/P2) + shfl cumsum + barrier-free substitution.
#define PA 68
__global__ __launch_bounds__(256) void phaseA_kernel()
{
    extern __shared__ float smA[];
    float* Ks = smA;
    float* Kt = Ks + 64 * PA;
    float* Qs = Kt + 64 * PA;
    float* U0 = Qs + 64 * PA;
    float* Ws = U0 + 64 * PA;
    float* Ms = Ws + 64 * PA;
    float* cs = Ms + 64 * PA;
    float* es = cs + 64;
    float* bv = es + 64;
    float* gv = bv + 64;

    const int unit = blockIdx.x;
    const int chunk = unit & (NC - 1);
    const int bh = unit >> 5;
    const int tid = threadIdx.x;
    const int t0 = chunk * 64;
    const int tx = tid & 15, ty = tid >> 4;

    const float* qg = d_q + ((size_t)bh * T + t0) * DK;
    const float* kg = d_k + ((size_t)bh * T + t0) * DK;
    const float* vg = d_v + ((size_t)bh * T + t0) * DK;

#pragma unroll
    for (int i = 0; i < 4; i++) {
        int p = tid + i * 256;
        int r = p >> 4, c4 = (p & 15) * 4;
        *reinterpret_cast<float4*>(Ks + r * PA + c4) = *reinterpret_cast<const float4*>(kg + r * 64 + c4);
        *reinterpret_cast<float4*>(Qs + r * PA + c4) = *reinterpret_cast<const float4*>(qg + r * 64 + c4);
        *reinterpret_cast<float4*>(U0 + r * PA + c4) = *reinterpret_cast<const float4*>(vg + r * 64 + c4);
    }
    if (tid < 64) {
        gv[tid] = d_g[(size_t)bh * T + t0 + tid];
        bv[tid] = d_beta[(size_t)bh * T + t0 + tid];
    }
    __syncthreads();
    // cumsum via 2-warp shfl scan
    if (tid < 64) {
        float v = gv[tid];
        for (int o = 1; o < 32; o <<= 1) {
            float n = __shfl_up_sync(0xffffffffu, v, o);
            if ((tid & 31) >= o) v += n;
        }
        cs[tid] = v;
    }
    __syncthreads();
    if (tid >= 32 && tid < 64) cs[tid] += cs[31];
    __syncthreads();
    if (tid < 64) {
        es[tid] = expf(cs[tid]);
        gv[tid] = expf(cs[63] - cs[tid]);
    }
    __syncthreads();
#pragma unroll
    for (int i = 0; i < 16; i++) {
        int p = tid + i * 256;
        int r = p >> 6, ccx = p & 63;
        float kvv = Ks[r * PA + ccx];
        Kt[ccx * PA + r] = kvv;
        Ws[r * PA + ccx] = bv[r] * es[r] * kvv;
        U0[r * PA + ccx] *= bv[r];
    }
    __syncthreads();

#define P1(Aptr, Bptr)                                                            \
    {                                                                             \
        _Pragma("unroll")                                                         \
        for (int i = 0; i < 4; i++)                                               \
            _Pragma("unroll")                                                     \
            for (int j = 0; j < 4; j++) acc[i][j] = 0.f;                          \
        for (int d4 = 0; d4 < 16; d4++) {                                         \
            float4 av[4];                                                         \
            _Pragma("unroll")                                                     \
            for (int i = 0; i < 4; i++)                                           \
                av[i] = *reinterpret_cast<const float4*>((Aptr) + (ty * 4 + i) * PA + d4 * 4); \
            const float* ap = reinterpret_cast<const float*>(av);                 \
            _Pragma("unroll")                                                     \
            for (int u = 0; u < 4; u++) {                                         \
                float4 rb = *reinterpret_cast<const float4*>((Bptr) + (d4 * 4 + u) * PA + tx * 4); \
                _Pragma("unroll")                                                 \
                for (int i = 0; i < 4; i++) {                                     \
                    float a = ap[i * 4 + u];                                      \
                    acc[i][0] = fmaf(a, rb.x, acc[i][0]);                         \
                    acc[i][1] = fmaf(a, rb.y, acc[i][1]);                         \
                    acc[i][2] = fmaf(a, rb.z, acc[i][2]);                         \
                    acc[i][3] = fmaf(a, rb.w, acc[i][3]);                         \
                }                                                                 \
            }                                                                     \
        }                                                                         \
    }
#define P2(Aptr, Bptr)                                                            \
    {                                                                             \
        _Pragma("unroll")                                                         \
        for (int i = 0; i < 4; i++)                                               \
            _Pragma("unroll")                                                     \
            for (int j = 0; j < 4; j++) acc[i][j] = 0.f;                          \
        for (int s = 0; s < 64; s++) {                                            \
            float4 ra = *reinterpret_cast<const float4*>((Aptr) + s * PA + ty * 4); \
            float4 rb = *reinterpret_cast<const float4*>((Bptr) + s * PA + tx * 4); \
            const float* rap = reinterpret_cast<const float*>(&ra);               \
            _Pragma("unroll")                                                     \
            for (int i = 0; i < 4; i++) {                                         \
                float a = rap[i];                                                 \
                acc[i][0] = fmaf(a, rb.x, acc[i][0]);                             \
                acc[i][1] = fmaf(a, rb.y, acc[i][1]);                             \
                acc[i][2] = fmaf(a, rb.z, acc[i][2]);                             \
                acc[i][3] = fmaf(a, rb.w, acc[i][3]);                             \
            }                                                                     \
        }                                                                         \
    }

    float acc[4][4];

    P1(Ks, Kt);
#pragma unroll
    for (int i = 0; i < 4; i++) {
        int t = ty * 4 + i;
#pragma unroll
        for (int j = 0; j < 4; j++) {
            int s = tx * 4 + j;
            Ms[t * PA + s] = (t > s) ? bv[t] * expf(cs[t] - cs[s]) * acc[i][j] : 0.f;
        }
    }
    __syncthreads();

    // barrier-free forward substitution: each thread owns one column of U0 or Ws
    if (tid < 128) {
        const int j = tid & 63;
        float* X = (tid < 64) ? U0 : Ws;
        for (int t = 1; t < 64; t++) {
            const float* mrow = Ms + t * PA;
            float a0 = 0.f, a1 = 0.f, a2 = 0.f, a3 = 0.f;
            int s = 0;
            for (; s + 4 <= t; s += 4) {
                a0 = fmaf(mrow[s],     X[s * PA + j],       a0);
                a1 = fmaf(mrow[s + 1], X[(s + 1) * PA + j], a1);
                a2 = fmaf(mrow[s + 2], X[(s + 2) * PA + j], a2);
                a3 = fmaf(mrow[s + 3], X[(s + 3) * PA + j], a3);
            }
            for (; s < t; s++) a0 = fmaf(mrow[s], X[s * PA + j], a0);
            X[t * PA + j] -= (a0 + a1) + (a2 + a3);
        }
    }
    __syncthreads();

    P1(Qs, Kt);
#pragma unroll
    for (int i = 0; i < 4; i++) {
        int t = ty * 4 + i;
#pragma unroll
        for (int j = 0; j < 4; j++) {
            int s = tx * 4 + j;
            Ms[t * PA + s] = (t >= s) ? expf(cs[t] - cs[s]) * acc[i][j] : 0.f;
        }
    }
#pragma unroll
    for (int i = 0; i < 16; i++) {
        int p = tid + i * 256;
        int r = p >> 6, ccx = p & 63;
        Ks[r * PA + ccx] *= gv[r];
    }
    __syncthreads();

    float* oOi = d_Oi + (size_t)unit * 4096;
    float* oQe = d_Qe + (size_t)unit * 4096;
    float* oSm = d_Sm + (size_t)unit * 4096;
    float* oSa = d_Sa + (size_t)unit * 4096;

    P1(Ms, U0);
#pragma unroll
    for (int i = 0; i < 4; i++)
        *reinterpret_cast<float4*>(oOi + (ty * 4 + i) * 64 + tx * 4) =
            make_float4(acc[i][0], acc[i][1], acc[i][2], acc[i][3]);

    P1(Ms, Ws);
#pragma unroll
    for (int i = 0; i < 4; i++) {
        int t = ty * 4 + i;
        float4 q4 = *reinterpret_cast<const float4*>(Qs + t * PA + tx * 4);
        float e = es[t];
        *reinterpret_cast<float4*>(oQe + t * 64 + tx * 4) =
            make_float4(e * q4.x - acc[i][0], e * q4.y - acc[i][1],
                        e * q4.z - acc[i][2], e * q4.w - acc[i][3]);
    }

    P2(Ks, Ws);
    {
        float ecc = es[63];
#pragma unroll
        for (int i = 0; i < 4; i++) {
            int a = ty * 4 + i;
            float4 v4;
            v4.x = ((a == tx * 4 + 0) ? ecc : 0.f) - acc[i][0];
            v4.y = ((a == tx * 4 + 1) ? ecc : 0.f) - acc[i][1];
            v4.z = ((a == tx * 4 + 2) ? ecc : 0.f) - acc[i][2];
            v4.w = ((a == tx * 4 + 3) ? ecc : 0.f) - acc[i][3];
            *reinterpret_cast<float4*>(oSm + a * 64 + tx * 4) = v4;
        }
    }
    P2(Ks, U0);
#pragma unroll
    for (int i = 0; i < 4; i++)
        *reinterpret_cast<float4*>(oSa + (ty * 4 + i) * 64 + tx * 4) =
            make_float4(acc[i][0], acc[i][1], acc[i][2], acc[i][3]);
#undef P1
#undef P2
}

#define PB 68
#define PS 36
__global__ __launch_bounds__(256) void phaseB_kernel()
{
    extern __shared__ float smB[];
    float* Qe = smB;
    float* Sm = Qe + 64 * PB;
    float* Sbuf0 = Sm + 64 * PB;
    float* Sbuf1 = Sbuf0 + 64 * PS;

    const int bh = blockIdx.x >> 1;
    const int half = blockIdx.x & 1;
    const int b = bh >> 4, h = bh & 15;
    const int tid = threadIdx.x;
    const int tx = tid & 7, ty = tid >> 3;

    for (int i = tid; i < 64 * PS * 2; i += 256) Sbuf0[i] = 0.f;
    __syncthreads();

    float* Sc = Sbuf0;
    float* Sn = Sbuf1;

    for (int c = 0; c < NC; c++) {
        const int unit = bh * NC + c;
        const float* qe_g = d_Qe + (size_t)unit * 4096;
        const float* sm_g = d_Sm + (size_t)unit * 4096;
#pragma unroll
        for (int i = 0; i < 4; i++) {
            int p = tid + i * 256;
            int r = p >> 4, c4 = (p & 15) * 4;
            *reinterpret_cast<float4*>(Qe + r * PB + c4) = *reinterpret_cast<const float4*>(qe_g + r * 64 + c4);
            *reinterpret_cast<float4*>(Sm + r * PB + c4) = *reinterpret_cast<const float4*>(sm_g + r * 64 + c4);
        }
        __syncthreads();

        const float* oi_g = d_Oi + (size_t)unit * 4096 + half * 32;
        const float* sa_g = d_Sa + (size_t)unit * 4096 + half * 32;
        const int r0 = ty * 2, r1 = ty * 2 + 1;

        float4 o0 = *reinterpret_cast<const float4*>(oi_g + r0 * 64 + tx * 4);
        float4 o1 = *reinterpret_cast<const float4*>(oi_g + r1 * 64 + tx * 4);
        float4 s0 = *reinterpret_cast<const float4*>(sa_g + r0 * 64 + tx * 4);
        float4 s1 = *reinterpret_cast<const float4*>(sa_g + r1 * 64 + tx * 4);

        for (int d = 0; d < 64; d++) {
            float4 rb = *reinterpret_cast<const float4*>(Sc + d * PS + tx * 4);
            float a0 = Qe[r0 * PB + d], a1 = Qe[r1 * PB + d];
            float m0 = Sm[r0 * PB + d], m1 = Sm[r1 * PB + d];
            o0.x = fmaf(a0, rb.x, o0.x); o0.y = fmaf(a0, rb.y, o0.y);
            o0.z = fmaf(a0, rb.z, o0.z); o0.w = fmaf(a0, rb.w, o0.w);
            o1.x = fmaf(a1, rb.x, o1.x); o1.y = fmaf(a1, rb.y, o1.y);
            o1.z = fmaf(a1, rb.z, o1.z); o1.w = fmaf(a1, rb.w, o1.w);
            s0.x = fmaf(m0, rb.x, s0.x); s0.y = fmaf(m0, rb.y, s0.y);
            s0.z = fmaf(m0, rb.z, s0.z); s0.w = fmaf(m0, rb.w, s0.w);
            s1.x = fmaf(m1, rb.x, s1.x); s1.y = fmaf(m1, rb.y, s1.y);
            s1.z = fmaf(m1, rb.z, s1.z); s1.w = fmaf(m1, rb.w, s1.w);
        }

        *reinterpret_cast<float4*>(d_o + (((size_t)(b * T + c * 64 + r0) * H + h) * 64 + half * 32 + tx * 4)) = o0;
        *reinterpret_cast<float4*>(d_o + (((size_t)(b * T + c * 64 + r1) * H + h) * 64 + half * 32 + tx * 4)) = o1;
        *reinterpret_cast<float4*>(Sn + r0 * PS + tx * 4) = s0;
        *reinterpret_cast<float4*>(Sn + r1 * PS + tx * 4) = s1;
        __syncthreads();
        float* tmp = Sc; Sc = Sn; Sn = tmp;
    }
}

// ---------------- gated RMSNorm -> fp16 hi/lo ----------------
__global__ __launch_bounds__(256) void rmsgate_kernel(const float* __restrict__ rms_w)
{
    const int row = blockIdx.x * 8 + (threadIdx.x >> 5);
    const int lane = threadIdx.x & 31;
    const float* orow = d_o + (size_t)row * 64;
    float2 ov = *reinterpret_cast<const float2*>(orow + lane * 2);
    float ss = ov.x * ov.x + ov.y * ov.y;
    for (int o = 16; o; o >>= 1) ss += __shfl_xor_sync(0xffffffffu, ss, o);
    const float r = rsqrtf(ss * (1.f / 64.f) + 1e-5f);

    const int bt = row >> 4, h = row & 15;
    float2 gv = *reinterpret_cast<const float2*>(d_gpre + (size_t)bt * C + h * 64 + lane * 2);
    float2 wv = *reinterpret_cast<const float2*>(rms_w + lane * 2);

    float rx = ov.x * r * wv.x * siluf(gv.x);
    float ry = ov.y * r * wv.y * siluf(gv.y);

    const size_t oidx = (size_t)bt * C + h * 64 + lane * 2;
    __half hx = __float2half_rn(rx);
    __half hy = __float2half_rn(ry);
    d_ogh[oidx] = hx;
    d_ogh[oidx + 1] = hy;
    d_ogl[oidx] = __float2half_rn(rx - __half2float(hx));
    d_ogl[oidx + 1] = __float2half_rn(ry - __half2float(hy));
}

// ---------------- launch ----------------
extern "C" void kernel_launch(void* const* d_in, const int* in_sizes, int n_in,
                              void* d_out, int out_size)
{
    const float* x       = (const float*)d_in[0];
    const float* Wq      = (const float*)d_in[1];
    const float* Wk      = (const float*)d_in[2];
    const float* Wv      = (const float*)d_in[3];
    const float* Wa      = (const float*)d_in[4];
    const float* Wb      = (const float*)d_in[5];
    const float* Wg      = (const float*)d_in[6];
    const float* Wo      = (const float*)d_in[7];
    const float* conv_q  = (const float*)d_in[8];
    const float* conv_k  = (const float*)d_in[9];
    const float* conv_v  = (const float*)d_in[10];
    const float* A_log   = (const float*)d_in[11];
    const float* dt_bias = (const float*)d_in[12];
    const float* rms_w   = (const float*)d_in[13];
    float* out = (float*)d_out;

    float *qpre, *kpre, *vpre, *gpre;
    __half *xh, *xl, *wt, *ogh, *ogl;
    cudaGetSymbolAddress((void**)&qpre, d_qpre);
    cudaGetSymbolAddress((void**)&kpre, d_kpre);
    cudaGetSymbolAddress((void**)&vpre, d_vpre);
    cudaGetSymbolAddress((void**)&gpre, d_gpre);
    cudaGetSymbolAddress((void**)&xh, d_xh);
    cudaGetSymbolAddress((void**)&xl, d_xl);
    cudaGetSymbolAddress((void**)&wt, d_Wt);
    cudaGetSymbolAddress((void**)&ogh, d_ogh);
    cudaGetSymbolAddress((void**)&ogl, d_ogl);

    const int smemA = (6 * 64 * PA + 4 * 64) * 4;
    const int smemB = (2 * 64 * PB + 2 * 64 * PS) * 4;
    cudaFuncSetAttribute(phaseA_kernel, cudaFuncAttributeMaxDynamicSharedMemorySize, smemA);
    cudaFuncSetAttribute(phaseB_kernel, cudaFuncAttributeMaxDynamicSharedMemorySize, smemB);
    cudaFuncSetAttribute(gemm_mma_kernel, cudaFuncAttributeMaxDynamicSharedMemorySize, GSMEM_BYTES);

    // 0) operand prep
    splitx_kernel<<<BT * D / 1024, 256>>>(x);
    wsplit_kernel<<<dim3(32, 32, 5), dim3(32, 8)>>>(Wq, Wk, Wv, Wg, Wo);

    // 1) projections q,k,v,g (mma.sync fp16x2, 2-stage, 2 CTA/SM)
    gemm_mma_kernel<<<dim3(8, 32, 4), 256, GSMEM_BYTES>>>(
        xh, xl, wt, qpre, kpre, vpre, gpre);

    // 2) conv + silu + relayout
    conv_silu_kernel<<<dim3(BT * C / 1024, 1, 3), 256>>>(conv_q, conv_k, conv_v);

    // 3) l2 norm
    l2norm_kernel<<<B * H * T / 8, 256>>>();

    // 4) g, beta
    gbeta2_kernel<<<BT / 64, 256>>>(x, Wa, Wb, A_log, dt_bias);

    // 5) chunked delta rule
    phaseA_kernel<<<UNITS, 256, smemA>>>();
    phaseB_kernel<<<B * H * 2, 256, smemB>>>();

    // 6) gated RMS norm (+ fp16 split)
    rmsgate_kernel<<<BT * H / 8, 256>>>(rms_w);

    // 7) output projection
    gemm_mma_kernel<<<dim3(8, 32, 1), 256, GSMEM_BYTES>>>(
        ogh, ogl, wt + 4ull * 1048576, out, out, out, out);
}